// round 10
// baseline (speedup 1.0000x reference)
#include <cuda_runtime.h>
#include <math.h>

#define D        64
#define DIMV     256
#define HNUM     4
#define NN       65
#define HIDDEN   512
#define SECTORS  11
#define BATCH    4096
#define QW_CNT   16640      /* N*DIM */
#define OW_OFF   16640
#define OB_OFF   82176
#define EDIM_ALL 82689
#define CHUNK    28
#define DP       65                        /* padded row stride in gram smem */
/* padded Gram layout: per (h,m) a 65x66 matrix, element [r][j] at r*66+j+1 */
#define GPM      (NN*66)                   /* 4290 floats per matrix */
#define GPH      (3*GPM)                   /* 12870 per head */
#define GRAM_TOT (HNUM*GPH)                /* 51480 floats */
#define SXS      66                        /* padded x row stride */

/* ---------------- scratch (static device globals; no allocation) -------- */
__device__ alignas(16) float g_stable[SECTORS*D];
__device__ alignas(16) float g_hidden[HIDDEN];
__device__ alignas(16) float g_qw[QW_CNT];
__device__ alignas(16) float g_ob[DIMV];
__device__ alignas(16) float g_om[DIMV];
__device__ float g_outb;
__device__ float g_C;
__device__ alignas(16) float g_scratch[DIMV*DIMV];   /* raw ow rows */
__device__ alignas(16) float g_gram[GRAM_TOT];
__device__ alignas(16) float g_Av[HNUM*NN];
__device__ alignas(16) float g_Bv[HNUM*NN];

/* ---------------- packed-f32 helpers ------------------------------------ */
typedef unsigned long long ull;
__device__ __forceinline__ ull f2u(float2 v){ ull u; __builtin_memcpy(&u,&v,8); return u; }
__device__ __forceinline__ ull pkdup(float x){ ull r; asm("mov.b64 %0, {%1,%1};" : "=l"(r) : "f"(x)); return r; }
__device__ __forceinline__ ull fma2(ull a, ull b, ull c){
    ull d; asm("fma.rn.f32x2 %0, %1, %2, %3;" : "=l"(d) : "l"(a), "l"(b), "l"(c)); return d;
}
__device__ __forceinline__ void upk(ull v, float& lo, float& hi){
    asm("mov.b64 {%0, %1}, %2;" : "=f"(lo), "=f"(hi) : "l"(v));
}
__device__ __forceinline__ float ex2f(float x){
    float r; asm("ex2.approx.ftz.f32 %0, %1;" : "=f"(r) : "f"(x)); return r;
}

/* ---------------- kernel 1: hypernetwork scalar part + sector table ----- */
__global__ void k_hyper(const float* __restrict__ z,
                        const float* __restrict__ Wh, const float* __restrict__ bh,
                        const float* __restrict__ Wc, const float* __restrict__ bc,
                        const float* __restrict__ Wi, const float* __restrict__ bi,
                        const float* __restrict__ W_ih, const float* __restrict__ W_hh,
                        const float* __restrict__ b_ih, const float* __restrict__ b_hh,
                        const float* __restrict__ W1, const float* __restrict__ b1,
                        const float* __restrict__ emb, const float* __restrict__ Wsp,
                        const float* __restrict__ bsp)
{
    __shared__ float sz[D], sh0[D], sc0[D], sinp[D], sg[4*D], sh[D];
    int t = threadIdx.x;   /* 512 threads */
    if (t < D) sz[t] = z[t];
    __syncthreads();
    if (t < 3*D) {
        int which = t / D, d = t % D;
        const float* W = (which==0) ? Wh : (which==1) ? Wc : Wi;
        const float* B = (which==0) ? bh : (which==1) ? bc : bi;
        float acc = B[d];
        #pragma unroll 8
        for (int k=0;k<D;k++) acc = fmaf(sz[k], W[d*D+k], acc);
        float v = tanhf(acc);
        if (which==0) sh0[d]=v; else if (which==1) sc0[d]=v; else sinp[d]=v;
    }
    __syncthreads();
    if (t < 4*D) {
        float acc = b_ih[t] + b_hh[t];
        #pragma unroll 8
        for (int k=0;k<D;k++) acc = fmaf(sinp[k], W_ih[t*D+k], acc);
        #pragma unroll 8
        for (int k=0;k<D;k++) acc = fmaf(sh0[k],  W_hh[t*D+k], acc);
        sg[t] = acc;
    }
    __syncthreads();
    if (t < D) {
        float ig = sg[t], fg = sg[D+t], gg = sg[2*D+t], og = sg[3*D+t];
        float si = 1.f/(1.f+expf(-ig));
        float sf = 1.f/(1.f+expf(-fg));
        float so = 1.f/(1.f+expf(-og));
        float c  = sf*sc0[t] + si*tanhf(gg);
        sh[t] = so*tanhf(c);
    }
    __syncthreads();
    {   /* hidden = relu(h @ W1.T + b1), all 512 threads */
        float acc = b1[t];
        #pragma unroll 8
        for (int d=0; d<D; d++) acc = fmaf(sh[d], W1[t*D+d], acc);
        g_hidden[t] = fmaxf(acc, 0.f);
    }
    /* sector table: s = emb @ Wsp.T + bsp  (704 dots of 256) */
    for (int idx = t; idx < SECTORS*D; idx += 512) {
        int sec = idx / D, d = idx % D;
        const float4* e4 = (const float4*)(emb + sec*DIMV);
        const float4* w4 = (const float4*)(Wsp + d*DIMV);
        float acc = 0.f;
        #pragma unroll 16
        for (int k=0;k<64;k++) {
            float4 a = e4[k]; float4 b = w4[k];
            acc = fmaf(a.x,b.x,fmaf(a.y,b.y,fmaf(a.z,b.z,fmaf(a.w,b.w,acc))));
        }
        g_stable[idx] = acc + bsp[d];
    }
}

/* ---------------- kernel 2: all rows of E = hidden @ W2.T + b2 ---------- */
__global__ void k_e_all(const float* __restrict__ W2, const float* __restrict__ b2)
{
    __shared__ alignas(16) float sh[HIDDEN];
    int t = threadIdx.x;                 /* 256 */
    for (int i=t;i<HIDDEN;i+=256) sh[i]=g_hidden[i];
    __syncthreads();
    int rbase = (blockIdx.x*8 + (t>>5))*4;
    int lane = t & 31;
    const float4* hv = (const float4*)sh;
    float4 h0 = hv[lane], h1 = hv[32+lane], h2 = hv[64+lane], h3 = hv[96+lane];
    float acc[4];
    #pragma unroll
    for (int rr=0; rr<4; rr++) {
        int r = rbase + rr;
        float a = 0.f;
        if (r < EDIM_ALL) {
            const float4* Wr = (const float4*)(W2 + (size_t)r*HIDDEN);
            float4 w0 = __ldcs(Wr+lane),    w1 = __ldcs(Wr+32+lane);
            float4 w2 = __ldcs(Wr+64+lane), w3 = __ldcs(Wr+96+lane);
            a = fmaf(w0.x,h0.x,fmaf(w0.y,h0.y,fmaf(w0.z,h0.z,w0.w*h0.w)));
            a = fmaf(w1.x,h1.x,fmaf(w1.y,h1.y,fmaf(w1.z,h1.z,fmaf(w1.w,h1.w,a))));
            a = fmaf(w2.x,h2.x,fmaf(w2.y,h2.y,fmaf(w2.z,h2.z,fmaf(w2.w,h2.w,a))));
            a = fmaf(w3.x,h3.x,fmaf(w3.y,h3.y,fmaf(w3.z,h3.z,fmaf(w3.w,h3.w,a))));
        }
        acc[rr] = a;
    }
    #pragma unroll
    for (int rr=0; rr<4; rr++) {
        #pragma unroll
        for (int o=16;o>0;o>>=1) acc[rr] += __shfl_xor_sync(0xffffffffu, acc[rr], o);
    }
    if (lane==0) {
        #pragma unroll
        for (int rr=0; rr<4; rr++) {
            int r = rbase + rr;
            if (r >= EDIM_ALL) break;
            float v = acc[rr] + b2[r];
            if (r < QW_CNT)          g_qw[r] = v;
            else if (r < OB_OFF)     g_scratch[r - OW_OFF] = v;
            else {
                int tt = r - OB_OFF;
                if (tt < 256)        g_ob[tt] = v;
                else if (tt < 512)   g_om[tt-256] = v;
                else                 g_outb = v;
            }
        }
    }
}

/* ---------------- kernel 3: Gram matrices + (i==0) v/C/Av/Bv ------------
   Gram written with log2(e) folded, in padded layout [r][j] -> r*66+j+1.  */
__global__ void __launch_bounds__(256)
k_gramfin(const float* __restrict__ num_w, const float* __restrict__ num_b,
          const float* __restrict__ cls)
{
    int h = blockIdx.x / NN;
    int i = blockIdx.x % NN;
    __shared__ alignas(16) float sA[NN*DP], sB[NN*DP];
    __shared__ alignas(16) float sv[D];
    __shared__ alignas(16) float som[DIMV];
    int t = threadIdx.x;                 /* 256 */
    int w = t >> 5, lane = t & 31;
    bool do_av = (i == 0);
    if (do_av) {
        som[t] = g_om[t];
        __syncthreads();                 /* block-uniform branch: safe */
        const float4* om4 = (const float4*)som;
        float4 m0 = om4[lane], m1 = om4[32+lane];
        for (int kk=w; kk<D; kk+=8) {
            const float4* row = (const float4*)(g_scratch + (h*D+kk)*256);
            float4 a0 = row[lane], a1 = row[32+lane];
            float acc = fmaf(a0.x,m0.x,fmaf(a0.y,m0.y,fmaf(a0.z,m0.z,a0.w*m0.w)));
            acc = fmaf(a1.x,m1.x,fmaf(a1.y,m1.y,fmaf(a1.z,m1.z,fmaf(a1.w,m1.w,acc))));
            #pragma unroll
            for (int o=16;o>0;o>>=1) acc += __shfl_xor_sync(0xffffffffu, acc, o);
            if (lane==0) sv[kk] = acc;
        }
        if (h==0 && w==0) {   /* C */
            float c = 0.f;
            #pragma unroll
            for (int q=0;q<8;q++) {
                int idx = q*32 + lane;
                c += (g_ob[idx] + cls[idx]) * som[idx];
            }
            #pragma unroll
            for (int o=16;o>0;o>>=1) c += __shfl_xor_sync(0xffffffffu, c, o);
            if (lane==0) g_C = c + g_outb;
        }
    }
    for (int idx=t; idx<NN*D; idx+=256) {
        int j = idx / D, d = idx % D;
        float q = g_qw[j*DIMV + h*D + d];
        float a, b;
        if (j==0) { a = 0.f; b = cls[h*D+d]*q; }
        else {
            a = num_w[(j-1)*DIMV + h*D + d]*q;
            b = num_b[(j-1)*DIMV + h*D + d]*q;
        }
        sA[j*DP+d]=a; sB[j*DP+d]=b;
    }
    __syncthreads();
    /* fold softmax scale AND log2(e) so attention can use raw ex2 */
    const float scale = 0.125f * 1.4426950408889634f;
    if (t < 3*NN) {
        int m = t / NN, j = t % NN;
        const float* P = (m==2) ? sB : sA;
        const float* Q = (m==0) ? sA : sB;
        const float* pr = P + i*DP;
        const float* qr = Q + j*DP;
        float acc=0.f;
        #pragma unroll 16
        for (int d=0; d<D; d++) acc = fmaf(pr[d], qr[d], acc);
        g_gram[h*GPH + m*GPM + i*66 + j + 1] = scale*acc;
    }
    if (do_av && t < 2*NN) {
        int sel = t / NN, j = t % NN;
        const float* row = (sel==0 ? sA : sB) + j*DP;
        float acc = 0.f;
        #pragma unroll 16
        for (int d=0; d<D; d++) acc = fmaf(row[d], sv[d], acc);
        if (sel==0) g_Av[h*NN+j] = acc; else g_Bv[h*NN+j] = acc;
    }
}

/* ---------------- kernel 4: attention logits + softmax (main) -----------
   L[i,j] = xi*xj*AA + xi*AB[i,j] + xj*AB[j,i] + BB   (scale+log2e folded)
   Lanes cover cols j=1..64 as packed pairs (f32x2 FMA, LDS.64);
   col j=0 (x0=0): L = xi*AB[i,0] + BB[i,0], scalar.
   SHFL butterfly warp-sum (redux.f32 not in sm_103 ISA); 2 batches/iter. */
__global__ void __launch_bounds__(1024,1)
k_attn(const float* __restrict__ X, const int* __restrict__ sector,
       float* __restrict__ out)
{
    extern __shared__ float smem[];
    float* sg = smem;                    /* GRAM_TOT floats, padded layout */
    float* sx = smem + GRAM_TOT;         /* CHUNK*66; x_j at c*66+j+1 */
    __shared__ int ssec[CHUNK];
    int t = threadIdx.x;                 /* 1024 */
    {
        const float4* src = (const float4*)g_gram;
        float4* dst = (float4*)sg;
        for (int i=t; i<GRAM_TOT/4; i+=1024) dst[i] = src[i];
    }
    int b0 = blockIdx.x * CHUNK;
    int nch = min(CHUNK, BATCH - b0);    /* 28 or 8: always even */
    if (t < nch) ssec[t] = sector[b0+t];
    __syncthreads();
    for (int idx=t; idx<nch*NN; idx+=1024) {
        int c = idx / NN, j = idx % NN;
        float v = 0.f;
        if (j > 0) {
            int b = b0 + c;
            v = X[b*D + (j-1)] + g_stable[ssec[c]*D + (j-1)];
        }
        sx[c*SXS + j + 1] = v;
    }
    __syncthreads();

    int warp = t >> 5, lane = t & 31;
    float* attn = out + BATCH;
    const long long bstride = (long long)HNUM*NN*NN;
    for (int pair = warp; pair < HNUM*NN; pair += 32) {
        int i = pair >> 2;
        int h = pair & 3;
        const float* AAs = sg + h*GPH;
        const float* ABs = AAs + GPM;
        const float* BBs = AAs + 2*GPM;
        /* packed coefficients for cols (1+2l, 2+2l): 8B-aligned LDS.64 */
        ull aaP = f2u(*(const float2*)(AAs + i*66 + 2 + 2*lane));
        ull abP = f2u(*(const float2*)(ABs + i*66 + 2 + 2*lane));
        ull bbP = f2u(*(const float2*)(BBs + i*66 + 2 + 2*lane));
        float2 bav = make_float2(ABs[(1+2*lane)*66 + i + 1],
                                 ABs[(2+2*lane)*66 + i + 1]);
        ull baP = f2u(bav);
        float ab0c = ABs[i*66 + 1];      /* AB[i,0] */
        float bb0c = BBs[i*66 + 1];      /* BB[i,0] */
        float* row = attn + (long long)b0*bstride + ((h*NN + i)*(long long)NN);
        for (int c=0; c<nch; c+=2) {
            const float* xa = sx + c*SXS;
            const float* xb = xa + SXS;
            ull xja = f2u(*(const float2*)(xa + 2 + 2*lane));
            ull xjb = f2u(*(const float2*)(xb + 2 + 2*lane));
            float xia = xa[i+1], xib = xb[i+1];
            ull La = fma2(pkdup(xia), fma2(xja, aaP, abP), fma2(xja, baP, bbP));
            ull Lb = fma2(pkdup(xib), fma2(xjb, aaP, abP), fma2(xjb, baP, bbP));
            float la0, la1, lb0, lb1;
            upk(La, la0, la1); upk(Lb, lb0, lb1);
            float ea0 = ex2f(la0), ea1 = ex2f(la1);
            float eb0 = ex2f(lb0), eb1 = ex2f(lb1);
            float e0a = ex2f(fmaf(xia, ab0c, bb0c));   /* col 0 */
            float e0b = ex2f(fmaf(xib, ab0c, bb0c));
            float sa = ea0 + ea1;
            float sb = eb0 + eb1;
            #pragma unroll
            for (int o=16;o>0;o>>=1) {
                sa += __shfl_xor_sync(0xffffffffu, sa, o);
                sb += __shfl_xor_sync(0xffffffffu, sb, o);
            }
            sa += e0a;
            sb += e0b;
            float ra = __fdividef(1.f, sa);
            float rb = __fdividef(1.f, sb);
            float* rowa = row;
            float* rowb = row + bstride;
            __stcs(rowa + 1 + 2*lane, ea0*ra);
            __stcs(rowa + 2 + 2*lane, ea1*ra);
            __stcs(rowb + 1 + 2*lane, eb0*rb);
            __stcs(rowb + 2 + 2*lane, eb1*rb);
            if (lane==0) {
                __stcs(rowa, e0a*ra);
                __stcs(rowb, e0b*rb);
            }
            row += 2*bstride;
        }
    }
}

/* ---------------- kernel 5: final[b] = C + sum p.(x.Av + Bv) ------------ */
__global__ void __launch_bounds__(256,1)
k_final(const float* __restrict__ X, const int* __restrict__ sector,
        float* __restrict__ out)
{
    __shared__ float sAv[HNUM*NN], sBv[HNUM*NN];
    int t = threadIdx.x;                 /* 256 */
    for (int i=t; i<HNUM*NN; i+=256) { sAv[i] = g_Av[i]; sBv[i] = g_Bv[i]; }
    __syncthreads();
    int wid = t >> 5, lane = t & 31;
    int b = blockIdx.x*8 + wid;
    if (b >= BATCH) return;
    int sec = sector[b];
    const float* Xb = X + b*D;
    const float* st = g_stable + sec*D;
    float x0 = (lane>0) ? (Xb[lane-1]  + st[lane-1])  : 0.f;   /* j=lane     */
    float x1 =            Xb[lane+31] + st[lane+31];           /* j=lane+32  */
    float x2 = (lane==0)? (Xb[63]      + st[63])      : 0.f;   /* j=64       */
    const float* attn = out + BATCH;
    const float* p = attn + ((long long)b*HNUM)*NN*NN;   /* rows i=0 of 4 heads */
    float acc = 0.f;
    #pragma unroll
    for (int h=0; h<HNUM; h++) {
        const float* ph = p + (long long)h*NN*NN;        /* row i=0 */
        float p0 = ph[lane];
        float p1 = ph[lane+32];
        acc = fmaf(p0, fmaf(x0, sAv[h*NN+lane],    sBv[h*NN+lane]),    acc);
        acc = fmaf(p1, fmaf(x1, sAv[h*NN+lane+32], sBv[h*NN+lane+32]), acc);
        if (lane==0) {
            float p2 = ph[64];
            acc = fmaf(p2, fmaf(x2, sAv[h*NN+64], sBv[h*NN+64]), acc);
        }
    }
    #pragma unroll
    for (int o=16;o>0;o>>=1) acc += __shfl_xor_sync(0xffffffffu, acc, o);
    if (lane==0) out[b] = acc + g_C;
}

/* ---------------- launch ------------------------------------------------ */
extern "C" void kernel_launch(void* const* d_in, const int* in_sizes, int n_in,
                              void* d_out, int out_size)
{
    const float* X      = (const float*)d_in[0];
    const float* z      = (const float*)d_in[1];
    const int*   sector = (const int*)  d_in[2];
    const float* emb    = (const float*)d_in[3];
    const float* Wsp    = (const float*)d_in[4];
    const float* bsp    = (const float*)d_in[5];
    const float* Wh     = (const float*)d_in[6];
    const float* bh     = (const float*)d_in[7];
    const float* Wc     = (const float*)d_in[8];
    const float* bc     = (const float*)d_in[9];
    const float* Wi     = (const float*)d_in[10];
    const float* bi     = (const float*)d_in[11];
    const float* W_ih   = (const float*)d_in[12];
    const float* W_hh   = (const float*)d_in[13];
    const float* b_ih   = (const float*)d_in[14];
    const float* b_hh   = (const float*)d_in[15];
    const float* num_w  = (const float*)d_in[16];
    const float* num_b  = (const float*)d_in[17];
    const float* cls    = (const float*)d_in[18];
    const float* W1     = (const float*)d_in[19];
    const float* b1     = (const float*)d_in[20];
    const float* W2     = (const float*)d_in[21];
    const float* b2     = (const float*)d_in[22];
    float* out = (float*)d_out;

    size_t smem4a = (size_t)(GRAM_TOT + CHUNK*SXS) * sizeof(float);   /* ~213 KB */
    cudaFuncSetAttribute(k_attn, cudaFuncAttributeMaxDynamicSharedMemorySize, (int)smem4a);

    k_hyper<<<1,512>>>(z,Wh,bh,Wc,bc,Wi,bi,W_ih,W_hh,b_ih,b_hh,W1,b1,emb,Wsp,bsp);
    k_e_all<<<(EDIM_ALL + 31)/32, 256>>>(W2,b2);
    k_gramfin<<<HNUM*NN,256>>>(num_w,num_b,cls);

    int nblk = (BATCH + CHUNK - 1) / CHUNK;    /* 147 */
    k_attn<<<nblk,1024,smem4a>>>(X,sector,out);   /* 4th launch -> ncu capture */
    k_final<<<(BATCH+7)/8,256>>>(X,sector,out);
}

// round 11
// speedup vs baseline: 1.0403x; 1.0403x over previous
#include <cuda_runtime.h>
#include <math.h>

#define D        64
#define DIMV     256
#define HNUM     4
#define NN       65
#define HIDDEN   512
#define SECTORS  11
#define BATCH    4096
#define QW_CNT   16640      /* N*DIM */
#define OW_OFF   16640
#define OB_OFF   82176
#define EDIM_ALL 82689
#define CHUNK    28
#define DP       65                        /* padded row stride in gram smem */
/* padded Gram layout: per (h,m) a 65x66 matrix, element [r][j] at r*66+j+1 */
#define GPM      (NN*66)                   /* 4290 floats per matrix */
#define GPH      (3*GPM)                   /* 12870 per head */
#define GRAM_TOT (HNUM*GPH)                /* 51480 floats */
#define SXS      66                        /* padded x row stride */

/* ---------------- scratch (static device globals; no allocation) -------- */
__device__ alignas(16) float g_stable[SECTORS*D];
__device__ alignas(16) float g_hidden[HIDDEN];
__device__ alignas(16) float g_qw[QW_CNT];
__device__ alignas(16) float g_ob[DIMV];
__device__ alignas(16) float g_om[DIMV];
__device__ float g_outb;
__device__ float g_C;
__device__ alignas(16) float g_scratch[DIMV*DIMV];   /* raw ow rows */
__device__ alignas(16) float g_gram[GRAM_TOT];
__device__ alignas(16) float g_Av[HNUM*NN];
__device__ alignas(16) float g_Bv[HNUM*NN];

__device__ __forceinline__ float ex2f(float x){
    float r; asm("ex2.approx.ftz.f32 %0, %1;" : "=f"(r) : "f"(x)); return r;
}

/* ---------------- kernel 1: hypernetwork scalar part + sector table ----- */
__global__ void k_hyper(const float* __restrict__ z,
                        const float* __restrict__ Wh, const float* __restrict__ bh,
                        const float* __restrict__ Wc, const float* __restrict__ bc,
                        const float* __restrict__ Wi, const float* __restrict__ bi,
                        const float* __restrict__ W_ih, const float* __restrict__ W_hh,
                        const float* __restrict__ b_ih, const float* __restrict__ b_hh,
                        const float* __restrict__ W1, const float* __restrict__ b1,
                        const float* __restrict__ emb, const float* __restrict__ Wsp,
                        const float* __restrict__ bsp)
{
    __shared__ float sz[D], sh0[D], sc0[D], sinp[D], sg[4*D], sh[D];
    int t = threadIdx.x;   /* 512 threads */
    if (t < D) sz[t] = z[t];
    __syncthreads();
    if (t < 3*D) {
        int which = t / D, d = t % D;
        const float* W = (which==0) ? Wh : (which==1) ? Wc : Wi;
        const float* B = (which==0) ? bh : (which==1) ? bc : bi;
        float acc = B[d];
        #pragma unroll 8
        for (int k=0;k<D;k++) acc = fmaf(sz[k], W[d*D+k], acc);
        float v = tanhf(acc);
        if (which==0) sh0[d]=v; else if (which==1) sc0[d]=v; else sinp[d]=v;
    }
    __syncthreads();
    if (t < 4*D) {
        float acc = b_ih[t] + b_hh[t];
        #pragma unroll 8
        for (int k=0;k<D;k++) acc = fmaf(sinp[k], W_ih[t*D+k], acc);
        #pragma unroll 8
        for (int k=0;k<D;k++) acc = fmaf(sh0[k],  W_hh[t*D+k], acc);
        sg[t] = acc;
    }
    __syncthreads();
    if (t < D) {
        float ig = sg[t], fg = sg[D+t], gg = sg[2*D+t], og = sg[3*D+t];
        float si = 1.f/(1.f+expf(-ig));
        float sf = 1.f/(1.f+expf(-fg));
        float so = 1.f/(1.f+expf(-og));
        float c  = sf*sc0[t] + si*tanhf(gg);
        sh[t] = so*tanhf(c);
    }
    __syncthreads();
    {   /* hidden = relu(h @ W1.T + b1), all 512 threads */
        float acc = b1[t];
        #pragma unroll 8
        for (int d=0; d<D; d++) acc = fmaf(sh[d], W1[t*D+d], acc);
        g_hidden[t] = fmaxf(acc, 0.f);
    }
    /* sector table: s = emb @ Wsp.T + bsp  (704 dots of 256) */
    for (int idx = t; idx < SECTORS*D; idx += 512) {
        int sec = idx / D, d = idx % D;
        const float4* e4 = (const float4*)(emb + sec*DIMV);
        const float4* w4 = (const float4*)(Wsp + d*DIMV);
        float acc = 0.f;
        #pragma unroll 16
        for (int k=0;k<64;k++) {
            float4 a = e4[k]; float4 b = w4[k];
            acc = fmaf(a.x,b.x,fmaf(a.y,b.y,fmaf(a.z,b.z,fmaf(a.w,b.w,acc))));
        }
        g_stable[idx] = acc + bsp[d];
    }
}

/* ---------------- kernel 2: all rows of E = hidden @ W2.T + b2 ---------- */
__global__ void k_e_all(const float* __restrict__ W2, const float* __restrict__ b2)
{
    __shared__ alignas(16) float sh[HIDDEN];
    int t = threadIdx.x;                 /* 256 */
    for (int i=t;i<HIDDEN;i+=256) sh[i]=g_hidden[i];
    __syncthreads();
    int rbase = (blockIdx.x*8 + (t>>5))*4;
    int lane = t & 31;
    const float4* hv = (const float4*)sh;
    float4 h0 = hv[lane], h1 = hv[32+lane], h2 = hv[64+lane], h3 = hv[96+lane];
    float acc[4];
    #pragma unroll
    for (int rr=0; rr<4; rr++) {
        int r = rbase + rr;
        float a = 0.f;
        if (r < EDIM_ALL) {
            const float4* Wr = (const float4*)(W2 + (size_t)r*HIDDEN);
            float4 w0 = __ldcs(Wr+lane),    w1 = __ldcs(Wr+32+lane);
            float4 w2 = __ldcs(Wr+64+lane), w3 = __ldcs(Wr+96+lane);
            a = fmaf(w0.x,h0.x,fmaf(w0.y,h0.y,fmaf(w0.z,h0.z,w0.w*h0.w)));
            a = fmaf(w1.x,h1.x,fmaf(w1.y,h1.y,fmaf(w1.z,h1.z,fmaf(w1.w,h1.w,a))));
            a = fmaf(w2.x,h2.x,fmaf(w2.y,h2.y,fmaf(w2.z,h2.z,fmaf(w2.w,h2.w,a))));
            a = fmaf(w3.x,h3.x,fmaf(w3.y,h3.y,fmaf(w3.z,h3.z,fmaf(w3.w,h3.w,a))));
        }
        acc[rr] = a;
    }
    #pragma unroll
    for (int rr=0; rr<4; rr++) {
        #pragma unroll
        for (int o=16;o>0;o>>=1) acc[rr] += __shfl_xor_sync(0xffffffffu, acc[rr], o);
    }
    if (lane==0) {
        #pragma unroll
        for (int rr=0; rr<4; rr++) {
            int r = rbase + rr;
            if (r >= EDIM_ALL) break;
            float v = acc[rr] + b2[r];
            if (r < QW_CNT)          g_qw[r] = v;
            else if (r < OB_OFF)     g_scratch[r - OW_OFF] = v;
            else {
                int tt = r - OB_OFF;
                if (tt < 256)        g_ob[tt] = v;
                else if (tt < 512)   g_om[tt-256] = v;
                else                 g_outb = v;
            }
        }
    }
}

/* ---------------- kernel 3: Gram matrices + (i==0) v/C/Av/Bv ------------
   Gram written with log2(e) folded, in padded layout [r][j] -> r*66+j+1.  */
__global__ void __launch_bounds__(256)
k_gramfin(const float* __restrict__ num_w, const float* __restrict__ num_b,
          const float* __restrict__ cls)
{
    int h = blockIdx.x / NN;
    int i = blockIdx.x % NN;
    __shared__ alignas(16) float sA[NN*DP], sB[NN*DP];
    __shared__ alignas(16) float sv[D];
    __shared__ alignas(16) float som[DIMV];
    int t = threadIdx.x;                 /* 256 */
    int w = t >> 5, lane = t & 31;
    bool do_av = (i == 0);
    if (do_av) {
        som[t] = g_om[t];
        __syncthreads();                 /* block-uniform branch: safe */
        const float4* om4 = (const float4*)som;
        float4 m0 = om4[lane], m1 = om4[32+lane];
        for (int kk=w; kk<D; kk+=8) {
            const float4* row = (const float4*)(g_scratch + (h*D+kk)*256);
            float4 a0 = row[lane], a1 = row[32+lane];
            float acc = fmaf(a0.x,m0.x,fmaf(a0.y,m0.y,fmaf(a0.z,m0.z,a0.w*m0.w)));
            acc = fmaf(a1.x,m1.x,fmaf(a1.y,m1.y,fmaf(a1.z,m1.z,fmaf(a1.w,m1.w,acc))));
            #pragma unroll
            for (int o=16;o>0;o>>=1) acc += __shfl_xor_sync(0xffffffffu, acc, o);
            if (lane==0) sv[kk] = acc;
        }
        if (h==0 && w==0) {   /* C */
            float c = 0.f;
            #pragma unroll
            for (int q=0;q<8;q++) {
                int idx = q*32 + lane;
                c += (g_ob[idx] + cls[idx]) * som[idx];
            }
            #pragma unroll
            for (int o=16;o>0;o>>=1) c += __shfl_xor_sync(0xffffffffu, c, o);
            if (lane==0) g_C = c + g_outb;
        }
    }
    for (int idx=t; idx<NN*D; idx+=256) {
        int j = idx / D, d = idx % D;
        float q = g_qw[j*DIMV + h*D + d];
        float a, b;
        if (j==0) { a = 0.f; b = cls[h*D+d]*q; }
        else {
            a = num_w[(j-1)*DIMV + h*D + d]*q;
            b = num_b[(j-1)*DIMV + h*D + d]*q;
        }
        sA[j*DP+d]=a; sB[j*DP+d]=b;
    }
    __syncthreads();
    /* fold softmax scale AND log2(e) so attention can use raw ex2 */
    const float scale = 0.125f * 1.4426950408889634f;
    if (t < 3*NN) {
        int m = t / NN, j = t % NN;
        const float* P = (m==2) ? sB : sA;
        const float* Q = (m==0) ? sA : sB;
        const float* pr = P + i*DP;
        const float* qr = Q + j*DP;
        float acc=0.f;
        #pragma unroll 16
        for (int d=0; d<D; d++) acc = fmaf(pr[d], qr[d], acc);
        g_gram[h*GPH + m*GPM + i*66 + j + 1] = scale*acc;
    }
    if (do_av && t < 2*NN) {
        int sel = t / NN, j = t % NN;
        const float* row = (sel==0 ? sA : sB) + j*DP;
        float acc = 0.f;
        #pragma unroll 16
        for (int d=0; d<D; d++) acc = fmaf(row[d], sv[d], acc);
        if (sel==0) g_Av[h*NN+j] = acc; else g_Bv[h*NN+j] = acc;
    }
}

/* ---------------- kernel 4: attention logits + softmax (main) -----------
   L[i,j] = xi*xj*AA + xi*AB[i,j] + xj*AB[j,i] + BB   (scale+log2e folded)
   Scalar math (short independent chains), lanes cover j=1..64 (2 each);
   col j=0 (x0=0): L = xi*AB[i,0] + BB[i,0] (lane-uniform, 1 FMA).
   4 batches per iteration -> 4 interleaved SHFL butterflies.             */
__global__ void __launch_bounds__(1024,1)
k_attn(const float* __restrict__ X, const int* __restrict__ sector,
       float* __restrict__ out)
{
    extern __shared__ float smem[];
    float* sg = smem;                    /* GRAM_TOT floats, padded layout */
    float* sx = smem + GRAM_TOT;         /* CHUNK*66; x_j at c*66+j+1 */
    __shared__ int ssec[CHUNK];
    int t = threadIdx.x;                 /* 1024 */
    {
        const float4* src = (const float4*)g_gram;
        float4* dst = (float4*)sg;
        for (int i=t; i<GRAM_TOT/4; i+=1024) dst[i] = src[i];
    }
    int b0 = blockIdx.x * CHUNK;
    int nch = min(CHUNK, BATCH - b0);    /* 28 or 8: both divisible by 4 */
    if (t < nch) ssec[t] = sector[b0+t];
    __syncthreads();
    for (int idx=t; idx<nch*NN; idx+=1024) {
        int c = idx / NN, j = idx % NN;
        float v = 0.f;
        if (j > 0) {
            int b = b0 + c;
            v = X[b*D + (j-1)] + g_stable[ssec[c]*D + (j-1)];
        }
        sx[c*SXS + j + 1] = v;
    }
    __syncthreads();

    int warp = t >> 5, lane = t & 31;
    float* attn = out + BATCH;
    const long long bstride = (long long)HNUM*NN*NN;
    for (int pair = warp; pair < HNUM*NN; pair += 32) {
        int i = pair >> 2;
        int h = pair & 3;
        const float* AAs = sg + h*GPH;
        const float* ABs = AAs + GPM;
        const float* BBs = AAs + 2*GPM;
        /* lane covers cols j0=1+lane, j1=33+lane */
        float aa0 = AAs[i*66 + 2 + lane],  aa1 = AAs[i*66 + 34 + lane];
        float ab0 = ABs[i*66 + 2 + lane],  ab1 = ABs[i*66 + 34 + lane];
        float bb0 = BBs[i*66 + 2 + lane],  bb1 = BBs[i*66 + 34 + lane];
        float ba0 = ABs[(1+lane)*66 + i + 1];
        float ba1 = ABs[(33+lane)*66 + i + 1];
        float ab0c = ABs[i*66 + 1];      /* AB[i,0] (lane-uniform) */
        float bb0c = BBs[i*66 + 1];      /* BB[i,0] */
        float* row = attn + (long long)b0*bstride + ((h*NN + i)*(long long)NN);
        for (int c=0; c<nch; c+=4) {
            float e0v[4], e1v[4], ecv[4], sums[4];
            #pragma unroll
            for (int q=0; q<4; q++) {
                const float* x = sx + (c+q)*SXS;
                float xi  = x[i+1];
                float xj0 = x[2+lane];
                float xj1 = x[34+lane];
                float e0 = ex2f(fmaf(xi, fmaf(xj0,aa0,ab0), fmaf(xj0,ba0,bb0)));
                float e1 = ex2f(fmaf(xi, fmaf(xj1,aa1,ab1), fmaf(xj1,ba1,bb1)));
                float ec = ex2f(fmaf(xi, ab0c, bb0c));   /* col 0, uniform */
                e0v[q]=e0; e1v[q]=e1; ecv[q]=ec;
                sums[q] = e0 + e1;
            }
            #pragma unroll
            for (int o=16;o>0;o>>=1) {
                #pragma unroll
                for (int q=0;q<4;q++)
                    sums[q] += __shfl_xor_sync(0xffffffffu, sums[q], o);
            }
            #pragma unroll
            for (int q=0;q<4;q++) {
                float r = __fdividef(1.f, sums[q] + ecv[q]);
                float* rw = row + q*bstride;
                __stcs(rw + 1 + lane,  e0v[q]*r);
                __stcs(rw + 33 + lane, e1v[q]*r);
                if (lane==0) __stcs(rw, ecv[q]*r);
            }
            row += 4*bstride;
        }
    }
}

/* ---------------- kernel 5: final[b] = C + sum p.(x.Av + Bv) ------------ */
__global__ void __launch_bounds__(256,1)
k_final(const float* __restrict__ X, const int* __restrict__ sector,
        float* __restrict__ out)
{
    __shared__ float sAv[HNUM*NN], sBv[HNUM*NN];
    int t = threadIdx.x;                 /* 256 */
    for (int i=t; i<HNUM*NN; i+=256) { sAv[i] = g_Av[i]; sBv[i] = g_Bv[i]; }
    __syncthreads();
    int wid = t >> 5, lane = t & 31;
    int b = blockIdx.x*8 + wid;
    if (b >= BATCH) return;
    int sec = sector[b];
    const float* Xb = X + b*D;
    const float* st = g_stable + sec*D;
    float x0 = (lane>0) ? (Xb[lane-1]  + st[lane-1])  : 0.f;   /* j=lane     */
    float x1 =            Xb[lane+31] + st[lane+31];           /* j=lane+32  */
    float x2 = (lane==0)? (Xb[63]      + st[63])      : 0.f;   /* j=64       */
    const float* attn = out + BATCH;
    const float* p = attn + ((long long)b*HNUM)*NN*NN;   /* rows i=0 of 4 heads */
    float acc = 0.f;
    #pragma unroll
    for (int h=0; h<HNUM; h++) {
        const float* ph = p + (long long)h*NN*NN;        /* row i=0 */
        float p0 = ph[lane];
        float p1 = ph[lane+32];
        acc = fmaf(p0, fmaf(x0, sAv[h*NN+lane],    sBv[h*NN+lane]),    acc);
        acc = fmaf(p1, fmaf(x1, sAv[h*NN+lane+32], sBv[h*NN+lane+32]), acc);
        if (lane==0) {
            float p2 = ph[64];
            acc = fmaf(p2, fmaf(x2, sAv[h*NN+64], sBv[h*NN+64]), acc);
        }
    }
    #pragma unroll
    for (int o=16;o>0;o>>=1) acc += __shfl_xor_sync(0xffffffffu, acc, o);
    if (lane==0) out[b] = acc + g_C;
}

/* ---------------- launch ------------------------------------------------ */
extern "C" void kernel_launch(void* const* d_in, const int* in_sizes, int n_in,
                              void* d_out, int out_size)
{
    const float* X      = (const float*)d_in[0];
    const float* z      = (const float*)d_in[1];
    const int*   sector = (const int*)  d_in[2];
    const float* emb    = (const float*)d_in[3];
    const float* Wsp    = (const float*)d_in[4];
    const float* bsp    = (const float*)d_in[5];
    const float* Wh     = (const float*)d_in[6];
    const float* bh     = (const float*)d_in[7];
    const float* Wc     = (const float*)d_in[8];
    const float* bc     = (const float*)d_in[9];
    const float* Wi     = (const float*)d_in[10];
    const float* bi     = (const float*)d_in[11];
    const float* W_ih   = (const float*)d_in[12];
    const float* W_hh   = (const float*)d_in[13];
    const float* b_ih   = (const float*)d_in[14];
    const float* b_hh   = (const float*)d_in[15];
    const float* num_w  = (const float*)d_in[16];
    const float* num_b  = (const float*)d_in[17];
    const float* cls    = (const float*)d_in[18];
    const float* W1     = (const float*)d_in[19];
    const float* b1     = (const float*)d_in[20];
    const float* W2     = (const float*)d_in[21];
    const float* b2     = (const float*)d_in[22];
    float* out = (float*)d_out;

    size_t smem4a = (size_t)(GRAM_TOT + CHUNK*SXS) * sizeof(float);   /* ~213 KB */
    cudaFuncSetAttribute(k_attn, cudaFuncAttributeMaxDynamicSharedMemorySize, (int)smem4a);

    k_hyper<<<1,512>>>(z,Wh,bh,Wc,bc,Wi,bi,W_ih,W_hh,b_ih,b_hh,W1,b1,emb,Wsp,bsp);
    k_e_all<<<(EDIM_ALL + 31)/32, 256>>>(W2,b2);
    k_gramfin<<<HNUM*NN,256>>>(num_w,num_b,cls);

    int nblk = (BATCH + CHUNK - 1) / CHUNK;    /* 147 */
    k_attn<<<nblk,1024,smem4a>>>(X,sector,out);   /* 4th launch -> ncu capture */
    k_final<<<(BATCH+7)/8,256>>>(X,sector,out);
}

// round 12
// speedup vs baseline: 1.0769x; 1.0352x over previous
#include <cuda_runtime.h>
#include <math.h>

#define D        64
#define DIMV     256
#define HNUM     4
#define NN       65
#define HIDDEN   512
#define SECTORS  11
#define BATCH    4096
#define QW_CNT   16640      /* N*DIM */
#define OW_OFF   16640
#define OB_OFF   82176
#define EDIM_ALL 82689
#define CHUNK    38
#define NCHUNKS  108                       /* 108*38 = 4104 >= 4096 */
#define DP       65                        /* padded row stride in gram smem */
/* padded Gram layout: per (h,m) a 65x66 matrix, element [r][j] at r*66+j+1 */
#define GPM      (NN*66)                   /* 4290 floats per matrix */
#define GPHP     12872                     /* 3*GPM=12870, padded to /4 and 16B */
#define SXS      66                        /* padded x row stride */

/* ---------------- scratch (static device globals; no allocation) -------- */
__device__ alignas(16) float g_stable[SECTORS*D];
__device__ alignas(16) float g_hidden[HIDDEN];
__device__ alignas(16) float g_qw[QW_CNT];
__device__ alignas(16) float g_ob[DIMV];
__device__ alignas(16) float g_om[DIMV];
__device__ float g_outb;
__device__ float g_C;
__device__ alignas(16) float g_scratch[DIMV*DIMV];   /* raw ow rows */
__device__ alignas(16) float g_gram[HNUM*GPHP];
__device__ alignas(16) float g_Av[HNUM*NN];
__device__ alignas(16) float g_Bv[HNUM*NN];

__device__ __forceinline__ float ex2f(float x){
    float r; asm("ex2.approx.ftz.f32 %0, %1;" : "=f"(r) : "f"(x)); return r;
}

/* ---------------- kernel 1: hypernetwork scalar part + sector table ----- */
__global__ void k_hyper(const float* __restrict__ z,
                        const float* __restrict__ Wh, const float* __restrict__ bh,
                        const float* __restrict__ Wc, const float* __restrict__ bc,
                        const float* __restrict__ Wi, const float* __restrict__ bi,
                        const float* __restrict__ W_ih, const float* __restrict__ W_hh,
                        const float* __restrict__ b_ih, const float* __restrict__ b_hh,
                        const float* __restrict__ W1, const float* __restrict__ b1,
                        const float* __restrict__ emb, const float* __restrict__ Wsp,
                        const float* __restrict__ bsp)
{
    __shared__ float sz[D], sh0[D], sc0[D], sinp[D], sg[4*D], sh[D];
    int t = threadIdx.x;   /* 512 threads */
    if (t < D) sz[t] = z[t];
    __syncthreads();
    if (t < 3*D) {
        int which = t / D, d = t % D;
        const float* W = (which==0) ? Wh : (which==1) ? Wc : Wi;
        const float* B = (which==0) ? bh : (which==1) ? bc : bi;
        float acc = B[d];
        #pragma unroll 8
        for (int k=0;k<D;k++) acc = fmaf(sz[k], W[d*D+k], acc);
        float v = tanhf(acc);
        if (which==0) sh0[d]=v; else if (which==1) sc0[d]=v; else sinp[d]=v;
    }
    __syncthreads();
    if (t < 4*D) {
        float acc = b_ih[t] + b_hh[t];
        #pragma unroll 8
        for (int k=0;k<D;k++) acc = fmaf(sinp[k], W_ih[t*D+k], acc);
        #pragma unroll 8
        for (int k=0;k<D;k++) acc = fmaf(sh0[k],  W_hh[t*D+k], acc);
        sg[t] = acc;
    }
    __syncthreads();
    if (t < D) {
        float ig = sg[t], fg = sg[D+t], gg = sg[2*D+t], og = sg[3*D+t];
        float si = 1.f/(1.f+expf(-ig));
        float sf = 1.f/(1.f+expf(-fg));
        float so = 1.f/(1.f+expf(-og));
        float c  = sf*sc0[t] + si*tanhf(gg);
        sh[t] = so*tanhf(c);
    }
    __syncthreads();
    {   /* hidden = relu(h @ W1.T + b1), all 512 threads */
        float acc = b1[t];
        #pragma unroll 8
        for (int d=0; d<D; d++) acc = fmaf(sh[d], W1[t*D+d], acc);
        g_hidden[t] = fmaxf(acc, 0.f);
    }
    /* sector table: s = emb @ Wsp.T + bsp  (704 dots of 256) */
    for (int idx = t; idx < SECTORS*D; idx += 512) {
        int sec = idx / D, d = idx % D;
        const float4* e4 = (const float4*)(emb + sec*DIMV);
        const float4* w4 = (const float4*)(Wsp + d*DIMV);
        float acc = 0.f;
        #pragma unroll 16
        for (int k=0;k<64;k++) {
            float4 a = e4[k]; float4 b = w4[k];
            acc = fmaf(a.x,b.x,fmaf(a.y,b.y,fmaf(a.z,b.z,fmaf(a.w,b.w,acc))));
        }
        g_stable[idx] = acc + bsp[d];
    }
}

/* ---------------- kernel 2: all rows of E = hidden @ W2.T + b2 ---------- */
__global__ void k_e_all(const float* __restrict__ W2, const float* __restrict__ b2)
{
    __shared__ alignas(16) float sh[HIDDEN];
    int t = threadIdx.x;                 /* 256 */
    for (int i=t;i<HIDDEN;i+=256) sh[i]=g_hidden[i];
    __syncthreads();
    int rbase = (blockIdx.x*8 + (t>>5))*4;
    int lane = t & 31;
    const float4* hv = (const float4*)sh;
    float4 h0 = hv[lane], h1 = hv[32+lane], h2 = hv[64+lane], h3 = hv[96+lane];
    float acc[4];
    #pragma unroll
    for (int rr=0; rr<4; rr++) {
        int r = rbase + rr;
        float a = 0.f;
        if (r < EDIM_ALL) {
            const float4* Wr = (const float4*)(W2 + (size_t)r*HIDDEN);
            float4 w0 = __ldcs(Wr+lane),    w1 = __ldcs(Wr+32+lane);
            float4 w2 = __ldcs(Wr+64+lane), w3 = __ldcs(Wr+96+lane);
            a = fmaf(w0.x,h0.x,fmaf(w0.y,h0.y,fmaf(w0.z,h0.z,w0.w*h0.w)));
            a = fmaf(w1.x,h1.x,fmaf(w1.y,h1.y,fmaf(w1.z,h1.z,fmaf(w1.w,h1.w,a))));
            a = fmaf(w2.x,h2.x,fmaf(w2.y,h2.y,fmaf(w2.z,h2.z,fmaf(w2.w,h2.w,a))));
            a = fmaf(w3.x,h3.x,fmaf(w3.y,h3.y,fmaf(w3.z,h3.z,fmaf(w3.w,h3.w,a))));
        }
        acc[rr] = a;
    }
    #pragma unroll
    for (int rr=0; rr<4; rr++) {
        #pragma unroll
        for (int o=16;o>0;o>>=1) acc[rr] += __shfl_xor_sync(0xffffffffu, acc[rr], o);
    }
    if (lane==0) {
        #pragma unroll
        for (int rr=0; rr<4; rr++) {
            int r = rbase + rr;
            if (r >= EDIM_ALL) break;
            float v = acc[rr] + b2[r];
            if (r < QW_CNT)          g_qw[r] = v;
            else if (r < OB_OFF)     g_scratch[r - OW_OFF] = v;
            else {
                int tt = r - OB_OFF;
                if (tt < 256)        g_ob[tt] = v;
                else if (tt < 512)   g_om[tt-256] = v;
                else                 g_outb = v;
            }
        }
    }
}

/* ---------------- kernel 3: Gram matrices + (i==0) v/C/Av/Bv ------------
   Gram written with log2(e) folded, padded layout [r][j] -> r*66+j+1,
   per-head stride GPHP (16B-aligned head bases).                         */
__global__ void __launch_bounds__(256)
k_gramfin(const float* __restrict__ num_w, const float* __restrict__ num_b,
          const float* __restrict__ cls)
{
    int h = blockIdx.x / NN;
    int i = blockIdx.x % NN;
    __shared__ alignas(16) float sA[NN*DP], sB[NN*DP];
    __shared__ alignas(16) float sv[D];
    __shared__ alignas(16) float som[DIMV];
    int t = threadIdx.x;                 /* 256 */
    int w = t >> 5, lane = t & 31;
    bool do_av = (i == 0);
    if (do_av) {
        som[t] = g_om[t];
        __syncthreads();                 /* block-uniform branch: safe */
        const float4* om4 = (const float4*)som;
        float4 m0 = om4[lane], m1 = om4[32+lane];
        for (int kk=w; kk<D; kk+=8) {
            const float4* row = (const float4*)(g_scratch + (h*D+kk)*256);
            float4 a0 = row[lane], a1 = row[32+lane];
            float acc = fmaf(a0.x,m0.x,fmaf(a0.y,m0.y,fmaf(a0.z,m0.z,a0.w*m0.w)));
            acc = fmaf(a1.x,m1.x,fmaf(a1.y,m1.y,fmaf(a1.z,m1.z,fmaf(a1.w,m1.w,acc))));
            #pragma unroll
            for (int o=16;o>0;o>>=1) acc += __shfl_xor_sync(0xffffffffu, acc, o);
            if (lane==0) sv[kk] = acc;
        }
        if (h==0 && w==0) {   /* C */
            float c = 0.f;
            #pragma unroll
            for (int q=0;q<8;q++) {
                int idx = q*32 + lane;
                c += (g_ob[idx] + cls[idx]) * som[idx];
            }
            #pragma unroll
            for (int o=16;o>0;o>>=1) c += __shfl_xor_sync(0xffffffffu, c, o);
            if (lane==0) g_C = c + g_outb;
        }
    }
    for (int idx=t; idx<NN*D; idx+=256) {
        int j = idx / D, d = idx % D;
        float q = g_qw[j*DIMV + h*D + d];
        float a, b;
        if (j==0) { a = 0.f; b = cls[h*D+d]*q; }
        else {
            a = num_w[(j-1)*DIMV + h*D + d]*q;
            b = num_b[(j-1)*DIMV + h*D + d]*q;
        }
        sA[j*DP+d]=a; sB[j*DP+d]=b;
    }
    __syncthreads();
    /* fold softmax scale AND log2(e) so attention can use raw ex2 */
    const float scale = 0.125f * 1.4426950408889634f;
    if (t < 3*NN) {
        int m = t / NN, j = t % NN;
        const float* P = (m==2) ? sB : sA;
        const float* Q = (m==0) ? sA : sB;
        const float* pr = P + i*DP;
        const float* qr = Q + j*DP;
        float acc=0.f;
        #pragma unroll 16
        for (int d=0; d<D; d++) acc = fmaf(pr[d], qr[d], acc);
        g_gram[h*GPHP + m*GPM + i*66 + j + 1] = scale*acc;
    }
    if (do_av && t < 2*NN) {
        int sel = t / NN, j = t % NN;
        const float* row = (sel==0 ? sA : sB) + j*DP;
        float acc = 0.f;
        #pragma unroll 16
        for (int d=0; d<D; d++) acc = fmaf(row[d], sv[d], acc);
        if (sel==0) g_Av[h*NN+j] = acc; else g_Bv[h*NN+j] = acc;
    }
}

/* ---------------- kernel 4: attention logits + softmax (main) -----------
   ONE HEAD per block: smem = head Gram (51.5KB) + x (10KB) -> 3 CTAs/SM,
   48 warps/SM (75% occ). 512 threads, warp per i-row, 2 batches/iter.
   L[i,j] = xi*xj*AA + xi*AB[i,j] + xj*AB[j,i] + BB  (scale+log2e folded)
   Lanes cover j0=1+lane, j1=33+lane; col j=0 (x0=0) is 1 uniform FMA.    */
__global__ void __launch_bounds__(512,3)
k_attn(const float* __restrict__ X, const int* __restrict__ sector,
       float* __restrict__ out)
{
    extern __shared__ float smem[];
    float* sg = smem;                    /* GPHP floats: this head's Gram */
    float* sx = smem + GPHP;             /* CHUNK*66; x_j at c*66+j+1 */
    __shared__ int ssec[CHUNK];
    int t = threadIdx.x;                 /* 512 */
    int chunk = blockIdx.x >> 2;
    int h     = blockIdx.x & 3;
    {
        const float4* src = (const float4*)(g_gram + h*GPHP);
        float4* dst = (float4*)sg;
        for (int i=t; i<GPHP/4; i+=512) dst[i] = src[i];
    }
    int b0 = chunk * CHUNK;
    int nch = min(CHUNK, BATCH - b0);    /* 38 or 30: both even */
    if (t < nch) ssec[t] = sector[b0+t];
    __syncthreads();
    for (int idx=t; idx<nch*NN; idx+=512) {
        int c = idx / NN, j = idx % NN;
        float v = 0.f;
        if (j > 0) {
            int b = b0 + c;
            v = X[b*D + (j-1)] + g_stable[ssec[c]*D + (j-1)];
        }
        sx[c*SXS + j + 1] = v;
    }
    __syncthreads();

    int warp = t >> 5, lane = t & 31;
    float* attn = out + BATCH;
    const long long bstride = (long long)HNUM*NN*NN;
    const float* AAs = sg;
    const float* ABs = sg + GPM;
    const float* BBs = sg + 2*GPM;
    for (int i = warp; i < NN; i += 16) {
        float aa0 = AAs[i*66 + 2 + lane],  aa1 = AAs[i*66 + 34 + lane];
        float ab0 = ABs[i*66 + 2 + lane],  ab1 = ABs[i*66 + 34 + lane];
        float bb0 = BBs[i*66 + 2 + lane],  bb1 = BBs[i*66 + 34 + lane];
        float ba0 = ABs[(1+lane)*66 + i + 1];
        float ba1 = ABs[(33+lane)*66 + i + 1];
        float ab0c = ABs[i*66 + 1];      /* AB[i,0] (lane-uniform) */
        float bb0c = BBs[i*66 + 1];      /* BB[i,0] */
        float* row = attn + (long long)b0*bstride + ((h*NN + i)*(long long)NN);
        for (int c=0; c<nch; c+=2) {
            const float* xA = sx + c*SXS;
            const float* xB = xA + SXS;
            float xiA = xA[i+1],   xiB = xB[i+1];
            float xj0A = xA[2+lane],  xj1A = xA[34+lane];
            float xj0B = xB[2+lane],  xj1B = xB[34+lane];
            float e0A = ex2f(fmaf(xiA, fmaf(xj0A,aa0,ab0), fmaf(xj0A,ba0,bb0)));
            float e1A = ex2f(fmaf(xiA, fmaf(xj1A,aa1,ab1), fmaf(xj1A,ba1,bb1)));
            float e0B = ex2f(fmaf(xiB, fmaf(xj0B,aa0,ab0), fmaf(xj0B,ba0,bb0)));
            float e1B = ex2f(fmaf(xiB, fmaf(xj1B,aa1,ab1), fmaf(xj1B,ba1,bb1)));
            float ecA = ex2f(fmaf(xiA, ab0c, bb0c));   /* col 0, uniform */
            float ecB = ex2f(fmaf(xiB, ab0c, bb0c));
            float sA = e0A + e1A;
            float sB = e0B + e1B;
            #pragma unroll
            for (int o=16;o>0;o>>=1) {
                sA += __shfl_xor_sync(0xffffffffu, sA, o);
                sB += __shfl_xor_sync(0xffffffffu, sB, o);
            }
            float rA = __fdividef(1.f, sA + ecA);
            float rB = __fdividef(1.f, sB + ecB);
            float* rowB = row + bstride;
            __stcs(row  + 1 + lane,  e0A*rA);
            __stcs(row  + 33 + lane, e1A*rA);
            __stcs(rowB + 1 + lane,  e0B*rB);
            __stcs(rowB + 33 + lane, e1B*rB);
            if (lane==0) {
                __stcs(row,  ecA*rA);
                __stcs(rowB, ecB*rB);
            }
            row += 2*bstride;
        }
    }
}

/* ---------------- kernel 5: final[b] = C + sum p.(x.Av + Bv) ------------ */
__global__ void __launch_bounds__(256,1)
k_final(const float* __restrict__ X, const int* __restrict__ sector,
        float* __restrict__ out)
{
    __shared__ float sAv[HNUM*NN], sBv[HNUM*NN];
    int t = threadIdx.x;                 /* 256 */
    for (int i=t; i<HNUM*NN; i+=256) { sAv[i] = g_Av[i]; sBv[i] = g_Bv[i]; }
    __syncthreads();
    int wid = t >> 5, lane = t & 31;
    int b = blockIdx.x*8 + wid;
    if (b >= BATCH) return;
    int sec = sector[b];
    const float* Xb = X + b*D;
    const float* st = g_stable + sec*D;
    float x0 = (lane>0) ? (Xb[lane-1]  + st[lane-1])  : 0.f;   /* j=lane     */
    float x1 =            Xb[lane+31] + st[lane+31];           /* j=lane+32  */
    float x2 = (lane==0)? (Xb[63]      + st[63])      : 0.f;   /* j=64       */
    const float* attn = out + BATCH;
    const float* p = attn + ((long long)b*HNUM)*NN*NN;   /* rows i=0 of 4 heads */
    float acc = 0.f;
    #pragma unroll
    for (int h=0; h<HNUM; h++) {
        const float* ph = p + (long long)h*NN*NN;        /* row i=0 */
        float p0 = ph[lane];
        float p1 = ph[lane+32];
        acc = fmaf(p0, fmaf(x0, sAv[h*NN+lane],    sBv[h*NN+lane]),    acc);
        acc = fmaf(p1, fmaf(x1, sAv[h*NN+lane+32], sBv[h*NN+lane+32]), acc);
        if (lane==0) {
            float p2 = ph[64];
            acc = fmaf(p2, fmaf(x2, sAv[h*NN+64], sBv[h*NN+64]), acc);
        }
    }
    #pragma unroll
    for (int o=16;o>0;o>>=1) acc += __shfl_xor_sync(0xffffffffu, acc, o);
    if (lane==0) out[b] = acc + g_C;
}

/* ---------------- launch ------------------------------------------------ */
extern "C" void kernel_launch(void* const* d_in, const int* in_sizes, int n_in,
                              void* d_out, int out_size)
{
    const float* X      = (const float*)d_in[0];
    const float* z      = (const float*)d_in[1];
    const int*   sector = (const int*)  d_in[2];
    const float* emb    = (const float*)d_in[3];
    const float* Wsp    = (const float*)d_in[4];
    const float* bsp    = (const float*)d_in[5];
    const float* Wh     = (const float*)d_in[6];
    const float* bh     = (const float*)d_in[7];
    const float* Wc     = (const float*)d_in[8];
    const float* bc     = (const float*)d_in[9];
    const float* Wi     = (const float*)d_in[10];
    const float* bi     = (const float*)d_in[11];
    const float* W_ih   = (const float*)d_in[12];
    const float* W_hh   = (const float*)d_in[13];
    const float* b_ih   = (const float*)d_in[14];
    const float* b_hh   = (const float*)d_in[15];
    const float* num_w  = (const float*)d_in[16];
    const float* num_b  = (const float*)d_in[17];
    const float* cls    = (const float*)d_in[18];
    const float* W1     = (const float*)d_in[19];
    const float* b1     = (const float*)d_in[20];
    const float* W2     = (const float*)d_in[21];
    const float* b2     = (const float*)d_in[22];
    float* out = (float*)d_out;

    size_t smem4a = (size_t)(GPHP + CHUNK*SXS) * sizeof(float);   /* ~60 KB */
    cudaFuncSetAttribute(k_attn, cudaFuncAttributeMaxDynamicSharedMemorySize, (int)smem4a);

    k_hyper<<<1,512>>>(z,Wh,bh,Wc,bc,Wi,bi,W_ih,W_hh,b_ih,b_hh,W1,b1,emb,Wsp,bsp);
    k_e_all<<<(EDIM_ALL + 31)/32, 256>>>(W2,b2);
    k_gramfin<<<HNUM*NN,256>>>(num_w,num_b,cls);

    k_attn<<<NCHUNKS*HNUM,512,smem4a>>>(X,sector,out);   /* 4th launch -> ncu */
    k_final<<<(BATCH+7)/8,256>>>(X,sector,out);
}

// round 13
// speedup vs baseline: 1.1840x; 1.0995x over previous
#include <cuda_runtime.h>
#include <math.h>

#define D        64
#define DIMV     256
#define HNUM     4
#define NN       65
#define HIDDEN   512
#define SECTORS  11
#define BATCH    4096
#define QW_CNT   16640      /* N*DIM */
#define OW_OFF   16640
#define OB_OFF   82176
#define EDIM_ALL 82689
#define CHUNK    38
#define NCHUNKS  108                       /* 108*38 = 4104 >= 4096 */
#define DP       65                        /* padded row stride in gram smem */
/* padded Gram layout: per (h,m) a 65x66 matrix, element [r][j] at r*66+j+1 */
#define GPM      (NN*66)                   /* 4290 floats per matrix */
#define GPHP     12872                     /* 3*GPM=12870, padded to /4 and 16B */
#define SXS      66                        /* padded x row stride */
#define EBLK_TOT 2585                      /* ceil(ceil(82689/4)/8) blocks total */
#define EBLK_A   1292                      /* first launch: rows [0, 41344) */

/* ---------------- scratch (static device globals; no allocation) -------- */
__device__ alignas(16) float g_stable[SECTORS*D];
__device__ alignas(16) float g_hidden[HIDDEN];
__device__ alignas(16) float g_qw[QW_CNT];
__device__ alignas(16) float g_ob[DIMV];
__device__ alignas(16) float g_om[DIMV];
__device__ float g_outb;
__device__ float g_C;
__device__ alignas(16) float g_scratch[DIMV*DIMV];   /* raw ow rows */
__device__ alignas(16) float g_gram[HNUM*GPHP];
__device__ alignas(16) float g_Av[HNUM*NN];
__device__ alignas(16) float g_Bv[HNUM*NN];

__device__ __forceinline__ float ex2f(float x){
    float r; asm("ex2.approx.ftz.f32 %0, %1;" : "=f"(r) : "f"(x)); return r;
}

/* ---------------- kernel 1: hypernetwork scalar part (LSTM + MLP1) ------ */
__global__ void k_hyper(const float* __restrict__ z,
                        const float* __restrict__ Wh, const float* __restrict__ bh,
                        const float* __restrict__ Wc, const float* __restrict__ bc,
                        const float* __restrict__ Wi, const float* __restrict__ bi,
                        const float* __restrict__ W_ih, const float* __restrict__ W_hh,
                        const float* __restrict__ b_ih, const float* __restrict__ b_hh,
                        const float* __restrict__ W1, const float* __restrict__ b1)
{
    __shared__ float sz[D], sh0[D], sc0[D], sinp[D], sg[4*D], sh[D];
    int t = threadIdx.x;   /* 512 threads */
    if (t < D) sz[t] = z[t];
    __syncthreads();
    if (t < 3*D) {
        int which = t / D, d = t % D;
        const float* W = (which==0) ? Wh : (which==1) ? Wc : Wi;
        const float* B = (which==0) ? bh : (which==1) ? bc : bi;
        float acc = B[d];
        #pragma unroll 8
        for (int k=0;k<D;k++) acc = fmaf(sz[k], W[d*D+k], acc);
        float v = tanhf(acc);
        if (which==0) sh0[d]=v; else if (which==1) sc0[d]=v; else sinp[d]=v;
    }
    __syncthreads();
    if (t < 4*D) {
        float acc = b_ih[t] + b_hh[t];
        #pragma unroll 8
        for (int k=0;k<D;k++) acc = fmaf(sinp[k], W_ih[t*D+k], acc);
        #pragma unroll 8
        for (int k=0;k<D;k++) acc = fmaf(sh0[k],  W_hh[t*D+k], acc);
        sg[t] = acc;
    }
    __syncthreads();
    if (t < D) {
        float ig = sg[t], fg = sg[D+t], gg = sg[2*D+t], og = sg[3*D+t];
        float si = 1.f/(1.f+expf(-ig));
        float sf = 1.f/(1.f+expf(-fg));
        float so = 1.f/(1.f+expf(-og));
        float c  = sf*sc0[t] + si*tanhf(gg);
        sh[t] = so*tanhf(c);
    }
    __syncthreads();
    {   /* hidden = relu(h @ W1.T + b1), all 512 threads */
        float acc = b1[t];
        #pragma unroll 8
        for (int d=0; d<D; d++) acc = fmaf(sh[d], W1[t*D+d], acc);
        g_hidden[t] = fmaxf(acc, 0.f);
    }
}

/* ---------------- kernel 1b: sector table, warp per output -------------- */
__global__ void k_stable(const float* __restrict__ emb, const float* __restrict__ Wsp,
                         const float* __restrict__ bsp)
{
    int w = blockIdx.x*8 + (threadIdx.x>>5);   /* 0..703 */
    if (w >= SECTORS*D) return;
    int lane = threadIdx.x & 31;
    int sec = w / D, d = w % D;
    const float4* e4 = (const float4*)(emb + sec*DIMV);
    const float4* w4 = (const float4*)(Wsp + d*DIMV);
    float acc = 0.f;
    #pragma unroll
    for (int it=0; it<2; it++) {
        float4 a = e4[it*32+lane]; float4 b = w4[it*32+lane];
        acc = fmaf(a.x,b.x,fmaf(a.y,b.y,fmaf(a.z,b.z,fmaf(a.w,b.w,acc))));
    }
    #pragma unroll
    for (int o=16;o>0;o>>=1) acc += __shfl_xor_sync(0xffffffffu, acc, o);
    if (lane==0) g_stable[w] = acc + bsp[d];
}

/* ---------------- kernel 2: rows of E = hidden @ W2.T + b2 --------------
   Warp handles 4 consecutive rows; launched in two halves (blk_off).      */
__global__ void k_e_all(const float* __restrict__ W2, const float* __restrict__ b2,
                        int blk_off)
{
    __shared__ alignas(16) float sh[HIDDEN];
    int t = threadIdx.x;                 /* 256 */
    for (int i=t;i<HIDDEN;i+=256) sh[i]=g_hidden[i];
    __syncthreads();
    int rbase = ((blk_off + blockIdx.x)*8 + (t>>5))*4;
    int lane = t & 31;
    const float4* hv = (const float4*)sh;
    float4 h0 = hv[lane], h1 = hv[32+lane], h2 = hv[64+lane], h3 = hv[96+lane];
    float acc[4];
    #pragma unroll
    for (int rr=0; rr<4; rr++) {
        int r = rbase + rr;
        float a = 0.f;
        if (r < EDIM_ALL) {
            const float4* Wr = (const float4*)(W2 + (size_t)r*HIDDEN);
            float4 w0 = __ldcs(Wr+lane),    w1 = __ldcs(Wr+32+lane);
            float4 w2 = __ldcs(Wr+64+lane), w3 = __ldcs(Wr+96+lane);
            a = fmaf(w0.x,h0.x,fmaf(w0.y,h0.y,fmaf(w0.z,h0.z,w0.w*h0.w)));
            a = fmaf(w1.x,h1.x,fmaf(w1.y,h1.y,fmaf(w1.z,h1.z,fmaf(w1.w,h1.w,a))));
            a = fmaf(w2.x,h2.x,fmaf(w2.y,h2.y,fmaf(w2.z,h2.z,fmaf(w2.w,h2.w,a))));
            a = fmaf(w3.x,h3.x,fmaf(w3.y,h3.y,fmaf(w3.z,h3.z,fmaf(w3.w,h3.w,a))));
        }
        acc[rr] = a;
    }
    #pragma unroll
    for (int rr=0; rr<4; rr++) {
        #pragma unroll
        for (int o=16;o>0;o>>=1) acc[rr] += __shfl_xor_sync(0xffffffffu, acc[rr], o);
    }
    if (lane==0) {
        #pragma unroll
        for (int rr=0; rr<4; rr++) {
            int r = rbase + rr;
            if (r >= EDIM_ALL) break;
            float v = acc[rr] + b2[r];
            if (r < QW_CNT)          g_qw[r] = v;
            else if (r < OB_OFF)     g_scratch[r - OW_OFF] = v;
            else {
                int tt = r - OB_OFF;
                if (tt < 256)        g_ob[tt] = v;
                else if (tt < 512)   g_om[tt-256] = v;
                else                 g_outb = v;
            }
        }
    }
}

/* ---------------- kernel 3: Gram matrices + (i==0) v/C/Av/Bv ------------ */
__global__ void __launch_bounds__(256)
k_gramfin(const float* __restrict__ num_w, const float* __restrict__ num_b,
          const float* __restrict__ cls)
{
    int h = blockIdx.x / NN;
    int i = blockIdx.x % NN;
    __shared__ alignas(16) float sA[NN*DP], sB[NN*DP];
    __shared__ alignas(16) float sv[D];
    __shared__ alignas(16) float som[DIMV];
    int t = threadIdx.x;                 /* 256 */
    int w = t >> 5, lane = t & 31;
    bool do_av = (i == 0);
    if (do_av) {
        som[t] = g_om[t];
        __syncthreads();                 /* block-uniform branch: safe */
        const float4* om4 = (const float4*)som;
        float4 m0 = om4[lane], m1 = om4[32+lane];
        for (int kk=w; kk<D; kk+=8) {
            const float4* row = (const float4*)(g_scratch + (h*D+kk)*256);
            float4 a0 = row[lane], a1 = row[32+lane];
            float acc = fmaf(a0.x,m0.x,fmaf(a0.y,m0.y,fmaf(a0.z,m0.z,a0.w*m0.w)));
            acc = fmaf(a1.x,m1.x,fmaf(a1.y,m1.y,fmaf(a1.z,m1.z,fmaf(a1.w,m1.w,acc))));
            #pragma unroll
            for (int o=16;o>0;o>>=1) acc += __shfl_xor_sync(0xffffffffu, acc, o);
            if (lane==0) sv[kk] = acc;
        }
        if (h==0 && w==0) {   /* C */
            float c = 0.f;
            #pragma unroll
            for (int q=0;q<8;q++) {
                int idx = q*32 + lane;
                c += (g_ob[idx] + cls[idx]) * som[idx];
            }
            #pragma unroll
            for (int o=16;o>0;o>>=1) c += __shfl_xor_sync(0xffffffffu, c, o);
            if (lane==0) g_C = c + g_outb;
        }
    }
    for (int idx=t; idx<NN*D; idx+=256) {
        int j = idx / D, d = idx % D;
        float q = g_qw[j*DIMV + h*D + d];
        float a, b;
        if (j==0) { a = 0.f; b = cls[h*D+d]*q; }
        else {
            a = num_w[(j-1)*DIMV + h*D + d]*q;
            b = num_b[(j-1)*DIMV + h*D + d]*q;
        }
        sA[j*DP+d]=a; sB[j*DP+d]=b;
    }
    __syncthreads();
    /* fold softmax scale AND log2(e) so attention can use raw ex2 */
    const float scale = 0.125f * 1.4426950408889634f;
    if (t < 3*NN) {
        int m = t / NN, j = t % NN;
        const float* P = (m==2) ? sB : sA;
        const float* Q = (m==0) ? sA : sB;
        const float* pr = P + i*DP;
        const float* qr = Q + j*DP;
        float acc=0.f;
        #pragma unroll 16
        for (int d=0; d<D; d++) acc = fmaf(pr[d], qr[d], acc);
        g_gram[h*GPHP + m*GPM + i*66 + j + 1] = scale*acc;
    }
    if (do_av && t < 2*NN) {
        int sel = t / NN, j = t % NN;
        const float* row = (sel==0 ? sA : sB) + j*DP;
        float acc = 0.f;
        #pragma unroll 16
        for (int d=0; d<D; d++) acc = fmaf(row[d], sv[d], acc);
        if (sel==0) g_Av[h*NN+j] = acc; else g_Bv[h*NN+j] = acc;
    }
}

/* ---------------- kernel 4: attention logits + softmax (main) -----------
   Identical to R12 (one head per block, 512 thr, 3 CTAs/SM).             */
__global__ void __launch_bounds__(512,3)
k_attn(const float* __restrict__ X, const int* __restrict__ sector,
       float* __restrict__ out)
{
    extern __shared__ float smem[];
    float* sg = smem;                    /* GPHP floats: this head's Gram */
    float* sx = smem + GPHP;             /* CHUNK*66; x_j at c*66+j+1 */
    __shared__ int ssec[CHUNK];
    int t = threadIdx.x;                 /* 512 */
    int chunk = blockIdx.x >> 2;
    int h     = blockIdx.x & 3;
    {
        const float4* src = (const float4*)(g_gram + h*GPHP);
        float4* dst = (float4*)sg;
        for (int i=t; i<GPHP/4; i+=512) dst[i] = src[i];
    }
    int b0 = chunk * CHUNK;
    int nch = min(CHUNK, BATCH - b0);    /* 38 or 30: both even */
    if (t < nch) ssec[t] = sector[b0+t];
    __syncthreads();
    for (int idx=t; idx<nch*NN; idx+=512) {
        int c = idx / NN, j = idx % NN;
        float v = 0.f;
        if (j > 0) {
            int b = b0 + c;
            v = X[b*D + (j-1)] + g_stable[ssec[c]*D + (j-1)];
        }
        sx[c*SXS + j + 1] = v;
    }
    __syncthreads();

    int warp = t >> 5, lane = t & 31;
    float* attn = out + BATCH;
    const long long bstride = (long long)HNUM*NN*NN;
    const float* AAs = sg;
    const float* ABs = sg + GPM;
    const float* BBs = sg + 2*GPM;
    for (int i = warp; i < NN; i += 16) {
        float aa0 = AAs[i*66 + 2 + lane],  aa1 = AAs[i*66 + 34 + lane];
        float ab0 = ABs[i*66 + 2 + lane],  ab1 = ABs[i*66 + 34 + lane];
        float bb0 = BBs[i*66 + 2 + lane],  bb1 = BBs[i*66 + 34 + lane];
        float ba0 = ABs[(1+lane)*66 + i + 1];
        float ba1 = ABs[(33+lane)*66 + i + 1];
        float ab0c = ABs[i*66 + 1];      /* AB[i,0] (lane-uniform) */
        float bb0c = BBs[i*66 + 1];      /* BB[i,0] */
        float* row = attn + (long long)b0*bstride + ((h*NN + i)*(long long)NN);
        for (int c=0; c<nch; c+=2) {
            const float* xA = sx + c*SXS;
            const float* xB = xA + SXS;
            float xiA = xA[i+1],   xiB = xB[i+1];
            float xj0A = xA[2+lane],  xj1A = xA[34+lane];
            float xj0B = xB[2+lane],  xj1B = xB[34+lane];
            float e0A = ex2f(fmaf(xiA, fmaf(xj0A,aa0,ab0), fmaf(xj0A,ba0,bb0)));
            float e1A = ex2f(fmaf(xiA, fmaf(xj1A,aa1,ab1), fmaf(xj1A,ba1,bb1)));
            float e0B = ex2f(fmaf(xiB, fmaf(xj0B,aa0,ab0), fmaf(xj0B,ba0,bb0)));
            float e1B = ex2f(fmaf(xiB, fmaf(xj1B,aa1,ab1), fmaf(xj1B,ba1,bb1)));
            float ecA = ex2f(fmaf(xiA, ab0c, bb0c));   /* col 0, uniform */
            float ecB = ex2f(fmaf(xiB, ab0c, bb0c));
            float sA = e0A + e1A;
            float sB = e0B + e1B;
            #pragma unroll
            for (int o=16;o>0;o>>=1) {
                sA += __shfl_xor_sync(0xffffffffu, sA, o);
                sB += __shfl_xor_sync(0xffffffffu, sB, o);
            }
            float rA = __fdividef(1.f, sA + ecA);
            float rB = __fdividef(1.f, sB + ecB);
            float* rowB = row + bstride;
            __stcs(row  + 1 + lane,  e0A*rA);
            __stcs(row  + 33 + lane, e1A*rA);
            __stcs(rowB + 1 + lane,  e0B*rB);
            __stcs(rowB + 33 + lane, e1B*rB);
            if (lane==0) {
                __stcs(row,  ecA*rA);
                __stcs(rowB, ecB*rB);
            }
            row += 2*bstride;
        }
    }
}

/* ---------------- kernel 5: final[b] = C + sum p.(x.Av + Bv) ------------ */
__global__ void __launch_bounds__(256,1)
k_final(const float* __restrict__ X, const int* __restrict__ sector,
        float* __restrict__ out)
{
    __shared__ float sAv[HNUM*NN], sBv[HNUM*NN];
    int t = threadIdx.x;                 /* 256 */
    for (int i=t; i<HNUM*NN; i+=256) { sAv[i] = g_Av[i]; sBv[i] = g_Bv[i]; }
    __syncthreads();
    int wid = t >> 5, lane = t & 31;
    int b = blockIdx.x*8 + wid;
    if (b >= BATCH) return;
    int sec = sector[b];
    const float* Xb = X + b*D;
    const float* st = g_stable + sec*D;
    float x0 = (lane>0) ? (Xb[lane-1]  + st[lane-1])  : 0.f;   /* j=lane     */
    float x1 =            Xb[lane+31] + st[lane+31];           /* j=lane+32  */
    float x2 = (lane==0)? (Xb[63]      + st[63])      : 0.f;   /* j=64       */
    const float* attn = out + BATCH;
    const float* p = attn + ((long long)b*HNUM)*NN*NN;   /* rows i=0 of 4 heads */
    float acc = 0.f;
    #pragma unroll
    for (int h=0; h<HNUM; h++) {
        const float* ph = p + (long long)h*NN*NN;        /* row i=0 */
        float p0 = ph[lane];
        float p1 = ph[lane+32];
        acc = fmaf(p0, fmaf(x0, sAv[h*NN+lane],    sBv[h*NN+lane]),    acc);
        acc = fmaf(p1, fmaf(x1, sAv[h*NN+lane+32], sBv[h*NN+lane+32]), acc);
        if (lane==0) {
            float p2 = ph[64];
            acc = fmaf(p2, fmaf(x2, sAv[h*NN+64], sBv[h*NN+64]), acc);
        }
    }
    #pragma unroll
    for (int o=16;o>0;o>>=1) acc += __shfl_xor_sync(0xffffffffu, acc, o);
    if (lane==0) out[b] = acc + g_C;
}

/* ---------------- launch ------------------------------------------------ */
extern "C" void kernel_launch(void* const* d_in, const int* in_sizes, int n_in,
                              void* d_out, int out_size)
{
    const float* X      = (const float*)d_in[0];
    const float* z      = (const float*)d_in[1];
    const int*   sector = (const int*)  d_in[2];
    const float* emb    = (const float*)d_in[3];
    const float* Wsp    = (const float*)d_in[4];
    const float* bsp    = (const float*)d_in[5];
    const float* Wh     = (const float*)d_in[6];
    const float* bh     = (const float*)d_in[7];
    const float* Wc     = (const float*)d_in[8];
    const float* bc     = (const float*)d_in[9];
    const float* Wi     = (const float*)d_in[10];
    const float* bi     = (const float*)d_in[11];
    const float* W_ih   = (const float*)d_in[12];
    const float* W_hh   = (const float*)d_in[13];
    const float* b_ih   = (const float*)d_in[14];
    const float* b_hh   = (const float*)d_in[15];
    const float* num_w  = (const float*)d_in[16];
    const float* num_b  = (const float*)d_in[17];
    const float* cls    = (const float*)d_in[18];
    const float* W1     = (const float*)d_in[19];
    const float* b1     = (const float*)d_in[20];
    const float* W2     = (const float*)d_in[21];
    const float* b2     = (const float*)d_in[22];
    float* out = (float*)d_out;

    size_t smem4a = (size_t)(GPHP + CHUNK*SXS) * sizeof(float);   /* ~60 KB */
    cudaFuncSetAttribute(k_attn, cudaFuncAttributeMaxDynamicSharedMemorySize, (int)smem4a);

    k_hyper<<<1,512>>>(z,Wh,bh,Wc,bc,Wi,bi,W_ih,W_hh,b_ih,b_hh,W1,b1);
    k_stable<<<(SECTORS*D+7)/8, 256>>>(emb,Wsp,bsp);
    k_e_all<<<EBLK_A, 256>>>(W2,b2,0);                       /* rows [0, 41344) */
    k_e_all<<<EBLK_TOT-EBLK_A, 256>>>(W2,b2,EBLK_A);         /* 4th -> ncu capture */
    k_gramfin<<<HNUM*NN,256>>>(num_w,num_b,cls);

    k_attn<<<NCHUNKS*HNUM,512,smem4a>>>(X,sector,out);
    k_final<<<(BATCH+7)/8,256>>>(X,sector,out);
}

// round 14
// speedup vs baseline: 1.2355x; 1.0435x over previous
#include <cuda_runtime.h>
#include <math.h>

#define D        64
#define DIMV     256
#define HNUM     4
#define NN       65
#define HIDDEN   512
#define SECTORS  11
#define BATCH    4096
#define QW_CNT   16640      /* N*DIM */
#define OW_OFF   16640
#define OB_OFF   82176
#define EDIM_ALL 82689
#define CHUNK    38
#define NCHUNKS  108                       /* 108*38 = 4104 >= 4096 */
#define DP       65                        /* padded row stride in gram smem */
/* padded Gram layout: per (h,m) a 65x66 matrix, element [r][j] at r*66+j+1 */
#define GPM      (NN*66)                   /* 4290 floats per matrix */
#define GPHP     12872                     /* 3*GPM=12870, padded to /4 and 16B */
#define SXS      66                        /* padded x row stride */
#define EROWS_PER_BLK 64                   /* 8 warps x 8 rows */
#define EBLKS    ((EDIM_ALL + EROWS_PER_BLK - 1)/EROWS_PER_BLK)   /* 1293 */

/* ---------------- scratch (static device globals; no allocation) -------- */
__device__ alignas(16) float g_stable[SECTORS*D];
__device__ alignas(16) float g_hidden[HIDDEN];
__device__ alignas(16) float g_qw[QW_CNT];
__device__ alignas(16) float g_ob[DIMV];
__device__ alignas(16) float g_om[DIMV];
__device__ float g_outb;
__device__ float g_C;
__device__ alignas(16) float g_scratch[DIMV*DIMV];   /* raw ow rows */
__device__ alignas(16) float g_gram[HNUM*GPHP];
__device__ alignas(16) float g_Av[HNUM*NN];
__device__ alignas(16) float g_Bv[HNUM*NN];

__device__ __forceinline__ float ex2f(float x){
    float r; asm("ex2.approx.ftz.f32 %0, %1;" : "=f"(r) : "f"(x)); return r;
}

/* ---------------- kernel 1: hypernetwork scalar part (LSTM + MLP1) ------ */
__global__ void k_hyper(const float* __restrict__ z,
                        const float* __restrict__ Wh, const float* __restrict__ bh,
                        const float* __restrict__ Wc, const float* __restrict__ bc,
                        const float* __restrict__ Wi, const float* __restrict__ bi,
                        const float* __restrict__ W_ih, const float* __restrict__ W_hh,
                        const float* __restrict__ b_ih, const float* __restrict__ b_hh,
                        const float* __restrict__ W1, const float* __restrict__ b1)
{
    __shared__ float sz[D], sh0[D], sc0[D], sinp[D], sg[4*D], sh[D];
    int t = threadIdx.x;   /* 512 threads */
    if (t < D) sz[t] = z[t];
    __syncthreads();
    if (t < 3*D) {
        int which = t / D, d = t % D;
        const float* W = (which==0) ? Wh : (which==1) ? Wc : Wi;
        const float* B = (which==0) ? bh : (which==1) ? bc : bi;
        float acc = B[d];
        #pragma unroll 8
        for (int k=0;k<D;k++) acc = fmaf(sz[k], W[d*D+k], acc);
        float v = tanhf(acc);
        if (which==0) sh0[d]=v; else if (which==1) sc0[d]=v; else sinp[d]=v;
    }
    __syncthreads();
    if (t < 4*D) {
        float acc = b_ih[t] + b_hh[t];
        #pragma unroll 8
        for (int k=0;k<D;k++) acc = fmaf(sinp[k], W_ih[t*D+k], acc);
        #pragma unroll 8
        for (int k=0;k<D;k++) acc = fmaf(sh0[k],  W_hh[t*D+k], acc);
        sg[t] = acc;
    }
    __syncthreads();
    if (t < D) {
        float ig = sg[t], fg = sg[D+t], gg = sg[2*D+t], og = sg[3*D+t];
        float si = 1.f/(1.f+expf(-ig));
        float sf = 1.f/(1.f+expf(-fg));
        float so = 1.f/(1.f+expf(-og));
        float c  = sf*sc0[t] + si*tanhf(gg);
        sh[t] = so*tanhf(c);
    }
    __syncthreads();
    {   /* hidden = relu(h @ W1.T + b1), all 512 threads */
        float acc = b1[t];
        #pragma unroll 8
        for (int d=0; d<D; d++) acc = fmaf(sh[d], W1[t*D+d], acc);
        g_hidden[t] = fmaxf(acc, 0.f);
    }
}

/* ---------------- kernel 1b: sector table, warp per output -------------- */
__global__ void k_stable(const float* __restrict__ emb, const float* __restrict__ Wsp,
                         const float* __restrict__ bsp)
{
    int w = blockIdx.x*8 + (threadIdx.x>>5);   /* 0..703 */
    if (w >= SECTORS*D) return;
    int lane = threadIdx.x & 31;
    int sec = w / D, d = w % D;
    const float4* e4 = (const float4*)(emb + sec*DIMV);
    const float4* w4 = (const float4*)(Wsp + d*DIMV);
    float acc = 0.f;
    #pragma unroll
    for (int it=0; it<2; it++) {
        float4 a = e4[it*32+lane]; float4 b = w4[it*32+lane];
        acc = fmaf(a.x,b.x,fmaf(a.y,b.y,fmaf(a.z,b.z,fmaf(a.w,b.w,acc))));
    }
    #pragma unroll
    for (int o=16;o>0;o>>=1) acc += __shfl_xor_sync(0xffffffffu, acc, o);
    if (lane==0) g_stable[w] = acc + bsp[d];
}

/* ---------------- kernel 2: all rows of E = hidden @ W2.T + b2 ----------
   Warp handles 8 rows (up to 32 outstanding LDG.128) to hide DRAM latency.
   Reg cap via launch_bounds keeps ~62% occupancy.                         */
__global__ void __launch_bounds__(256,5)
k_e_all(const float* __restrict__ W2, const float* __restrict__ b2)
{
    __shared__ alignas(16) float sh[HIDDEN];
    int t = threadIdx.x;                 /* 256 */
    for (int i=t;i<HIDDEN;i+=256) sh[i]=g_hidden[i];
    __syncthreads();
    int rbase = (blockIdx.x*8 + (t>>5))*8;
    int lane = t & 31;
    const float4* hv = (const float4*)sh;
    float4 h0 = hv[lane], h1 = hv[32+lane], h2 = hv[64+lane], h3 = hv[96+lane];
    float acc[8];
    #pragma unroll
    for (int rr=0; rr<8; rr++) {
        int r = rbase + rr;
        float a = 0.f;
        if (r < EDIM_ALL) {
            const float4* Wr = (const float4*)(W2 + (size_t)r*HIDDEN);
            float4 w0 = __ldcs(Wr+lane),    w1 = __ldcs(Wr+32+lane);
            float4 w2 = __ldcs(Wr+64+lane), w3 = __ldcs(Wr+96+lane);
            a = fmaf(w0.x,h0.x,fmaf(w0.y,h0.y,fmaf(w0.z,h0.z,w0.w*h0.w)));
            a = fmaf(w1.x,h1.x,fmaf(w1.y,h1.y,fmaf(w1.z,h1.z,fmaf(w1.w,h1.w,a))));
            a = fmaf(w2.x,h2.x,fmaf(w2.y,h2.y,fmaf(w2.z,h2.z,fmaf(w2.w,h2.w,a))));
            a = fmaf(w3.x,h3.x,fmaf(w3.y,h3.y,fmaf(w3.z,h3.z,fmaf(w3.w,h3.w,a))));
        }
        acc[rr] = a;
    }
    #pragma unroll
    for (int rr=0; rr<8; rr++) {
        #pragma unroll
        for (int o=16;o>0;o>>=1) acc[rr] += __shfl_xor_sync(0xffffffffu, acc[rr], o);
    }
    if (lane==0) {
        #pragma unroll
        for (int rr=0; rr<8; rr++) {
            int r = rbase + rr;
            if (r >= EDIM_ALL) break;
            float v = acc[rr] + b2[r];
            if (r < QW_CNT)          g_qw[r] = v;
            else if (r < OB_OFF)     g_scratch[r - OW_OFF] = v;
            else {
                int tt = r - OB_OFF;
                if (tt < 256)        g_ob[tt] = v;
                else if (tt < 512)   g_om[tt-256] = v;
                else                 g_outb = v;
            }
        }
    }
}

/* ---------------- kernel 3: Gram matrices + (i==0) v/C/Av/Bv ------------ */
__global__ void __launch_bounds__(256)
k_gramfin(const float* __restrict__ num_w, const float* __restrict__ num_b,
          const float* __restrict__ cls)
{
    int h = blockIdx.x / NN;
    int i = blockIdx.x % NN;
    __shared__ alignas(16) float sA[NN*DP], sB[NN*DP];
    __shared__ alignas(16) float sv[D];
    __shared__ alignas(16) float som[DIMV];
    int t = threadIdx.x;                 /* 256 */
    int w = t >> 5, lane = t & 31;
    bool do_av = (i == 0);
    if (do_av) {
        som[t] = g_om[t];
        __syncthreads();                 /* block-uniform branch: safe */
        const float4* om4 = (const float4*)som;
        float4 m0 = om4[lane], m1 = om4[32+lane];
        for (int kk=w; kk<D; kk+=8) {
            const float4* row = (const float4*)(g_scratch + (h*D+kk)*256);
            float4 a0 = row[lane], a1 = row[32+lane];
            float acc = fmaf(a0.x,m0.x,fmaf(a0.y,m0.y,fmaf(a0.z,m0.z,a0.w*m0.w)));
            acc = fmaf(a1.x,m1.x,fmaf(a1.y,m1.y,fmaf(a1.z,m1.z,fmaf(a1.w,m1.w,acc))));
            #pragma unroll
            for (int o=16;o>0;o>>=1) acc += __shfl_xor_sync(0xffffffffu, acc, o);
            if (lane==0) sv[kk] = acc;
        }
        if (h==0 && w==0) {   /* C */
            float c = 0.f;
            #pragma unroll
            for (int q=0;q<8;q++) {
                int idx = q*32 + lane;
                c += (g_ob[idx] + cls[idx]) * som[idx];
            }
            #pragma unroll
            for (int o=16;o>0;o>>=1) c += __shfl_xor_sync(0xffffffffu, c, o);
            if (lane==0) g_C = c + g_outb;
        }
    }
    for (int idx=t; idx<NN*D; idx+=256) {
        int j = idx / D, d = idx % D;
        float q = g_qw[j*DIMV + h*D + d];
        float a, b;
        if (j==0) { a = 0.f; b = cls[h*D+d]*q; }
        else {
            a = num_w[(j-1)*DIMV + h*D + d]*q;
            b = num_b[(j-1)*DIMV + h*D + d]*q;
        }
        sA[j*DP+d]=a; sB[j*DP+d]=b;
    }
    __syncthreads();
    /* fold softmax scale AND log2(e) so attention can use raw ex2 */
    const float scale = 0.125f * 1.4426950408889634f;
    if (t < 3*NN) {
        int m = t / NN, j = t % NN;
        const float* P = (m==2) ? sB : sA;
        const float* Q = (m==0) ? sA : sB;
        const float* pr = P + i*DP;
        const float* qr = Q + j*DP;
        float acc=0.f;
        #pragma unroll 16
        for (int d=0; d<D; d++) acc = fmaf(pr[d], qr[d], acc);
        g_gram[h*GPHP + m*GPM + i*66 + j + 1] = scale*acc;
    }
    if (do_av && t < 2*NN) {
        int sel = t / NN, j = t % NN;
        const float* row = (sel==0 ? sA : sB) + j*DP;
        float acc = 0.f;
        #pragma unroll 16
        for (int d=0; d<D; d++) acc = fmaf(row[d], sv[d], acc);
        if (sel==0) g_Av[h*NN+j] = acc; else g_Bv[h*NN+j] = acc;
    }
}

/* ---------------- kernel 4: attention logits + softmax (main) -----------
   One head per block, 512 thr, 3 CTAs/SM (proven R12/R13 config).        */
__global__ void __launch_bounds__(512,3)
k_attn(const float* __restrict__ X, const int* __restrict__ sector,
       float* __restrict__ out)
{
    extern __shared__ float smem[];
    float* sg = smem;                    /* GPHP floats: this head's Gram */
    float* sx = smem + GPHP;             /* CHUNK*66; x_j at c*66+j+1 */
    __shared__ int ssec[CHUNK];
    int t = threadIdx.x;                 /* 512 */
    int chunk = blockIdx.x >> 2;
    int h     = blockIdx.x & 3;
    {
        const float4* src = (const float4*)(g_gram + h*GPHP);
        float4* dst = (float4*)sg;
        for (int i=t; i<GPHP/4; i+=512) dst[i] = src[i];
    }
    int b0 = chunk * CHUNK;
    int nch = min(CHUNK, BATCH - b0);    /* 38 or 30: both even */
    if (t < nch) ssec[t] = sector[b0+t];
    __syncthreads();
    for (int idx=t; idx<nch*NN; idx+=512) {
        int c = idx / NN, j = idx % NN;
        float v = 0.f;
        if (j > 0) {
            int b = b0 + c;
            v = X[b*D + (j-1)] + g_stable[ssec[c]*D + (j-1)];
        }
        sx[c*SXS + j + 1] = v;
    }
    __syncthreads();

    int warp = t >> 5, lane = t & 31;
    float* attn = out + BATCH;
    const long long bstride = (long long)HNUM*NN*NN;
    const float* AAs = sg;
    const float* ABs = sg + GPM;
    const float* BBs = sg + 2*GPM;
    for (int i = warp; i < NN; i += 16) {
        float aa0 = AAs[i*66 + 2 + lane],  aa1 = AAs[i*66 + 34 + lane];
        float ab0 = ABs[i*66 + 2 + lane],  ab1 = ABs[i*66 + 34 + lane];
        float bb0 = BBs[i*66 + 2 + lane],  bb1 = BBs[i*66 + 34 + lane];
        float ba0 = ABs[(1+lane)*66 + i + 1];
        float ba1 = ABs[(33+lane)*66 + i + 1];
        float ab0c = ABs[i*66 + 1];      /* AB[i,0] (lane-uniform) */
        float bb0c = BBs[i*66 + 1];      /* BB[i,0] */
        float* row = attn + (long long)b0*bstride + ((h*NN + i)*(long long)NN);
        for (int c=0; c<nch; c+=2) {
            const float* xA = sx + c*SXS;
            const float* xB = xA + SXS;
            float xiA = xA[i+1],   xiB = xB[i+1];
            float xj0A = xA[2+lane],  xj1A = xA[34+lane];
            float xj0B = xB[2+lane],  xj1B = xB[34+lane];
            float e0A = ex2f(fmaf(xiA, fmaf(xj0A,aa0,ab0), fmaf(xj0A,ba0,bb0)));
            float e1A = ex2f(fmaf(xiA, fmaf(xj1A,aa1,ab1), fmaf(xj1A,ba1,bb1)));
            float e0B = ex2f(fmaf(xiB, fmaf(xj0B,aa0,ab0), fmaf(xj0B,ba0,bb0)));
            float e1B = ex2f(fmaf(xiB, fmaf(xj1B,aa1,ab1), fmaf(xj1B,ba1,bb1)));
            float ecA = ex2f(fmaf(xiA, ab0c, bb0c));   /* col 0, uniform */
            float ecB = ex2f(fmaf(xiB, ab0c, bb0c));
            float sA = e0A + e1A;
            float sB = e0B + e1B;
            #pragma unroll
            for (int o=16;o>0;o>>=1) {
                sA += __shfl_xor_sync(0xffffffffu, sA, o);
                sB += __shfl_xor_sync(0xffffffffu, sB, o);
            }
            float rA = __fdividef(1.f, sA + ecA);
            float rB = __fdividef(1.f, sB + ecB);
            float* rowB = row + bstride;
            __stcs(row  + 1 + lane,  e0A*rA);
            __stcs(row  + 33 + lane, e1A*rA);
            __stcs(rowB + 1 + lane,  e0B*rB);
            __stcs(rowB + 33 + lane, e1B*rB);
            if (lane==0) {
                __stcs(row,  ecA*rA);
                __stcs(rowB, ecB*rB);
            }
            row += 2*bstride;
        }
    }
}

/* ---------------- kernel 5: final[b] = C + sum p.(x.Av + Bv) ------------ */
__global__ void __launch_bounds__(256,1)
k_final(const float* __restrict__ X, const int* __restrict__ sector,
        float* __restrict__ out)
{
    __shared__ float sAv[HNUM*NN], sBv[HNUM*NN];
    int t = threadIdx.x;                 /* 256 */
    for (int i=t; i<HNUM*NN; i+=256) { sAv[i] = g_Av[i]; sBv[i] = g_Bv[i]; }
    __syncthreads();
    int wid = t >> 5, lane = t & 31;
    int b = blockIdx.x*8 + wid;
    if (b >= BATCH) return;
    int sec = sector[b];
    const float* Xb = X + b*D;
    const float* st = g_stable + sec*D;
    float x0 = (lane>0) ? (Xb[lane-1]  + st[lane-1])  : 0.f;   /* j=lane     */
    float x1 =            Xb[lane+31] + st[lane+31];           /* j=lane+32  */
    float x2 = (lane==0)? (Xb[63]      + st[63])      : 0.f;   /* j=64       */
    const float* attn = out + BATCH;
    const float* p = attn + ((long long)b*HNUM)*NN*NN;   /* rows i=0 of 4 heads */
    float acc = 0.f;
    #pragma unroll
    for (int h=0; h<HNUM; h++) {
        const float* ph = p + (long long)h*NN*NN;        /* row i=0 */
        float p0 = ph[lane];
        float p1 = ph[lane+32];
        acc = fmaf(p0, fmaf(x0, sAv[h*NN+lane],    sBv[h*NN+lane]),    acc);
        acc = fmaf(p1, fmaf(x1, sAv[h*NN+lane+32], sBv[h*NN+lane+32]), acc);
        if (lane==0) {
            float p2 = ph[64];
            acc = fmaf(p2, fmaf(x2, sAv[h*NN+64], sBv[h*NN+64]), acc);
        }
    }
    #pragma unroll
    for (int o=16;o>0;o>>=1) acc += __shfl_xor_sync(0xffffffffu, acc, o);
    if (lane==0) out[b] = acc + g_C;
}

/* ---------------- launch ------------------------------------------------ */
extern "C" void kernel_launch(void* const* d_in, const int* in_sizes, int n_in,
                              void* d_out, int out_size)
{
    const float* X      = (const float*)d_in[0];
    const float* z      = (const float*)d_in[1];
    const int*   sector = (const int*)  d_in[2];
    const float* emb    = (const float*)d_in[3];
    const float* Wsp    = (const float*)d_in[4];
    const float* bsp    = (const float*)d_in[5];
    const float* Wh     = (const float*)d_in[6];
    const float* bh     = (const float*)d_in[7];
    const float* Wc     = (const float*)d_in[8];
    const float* bc     = (const float*)d_in[9];
    const float* Wi     = (const float*)d_in[10];
    const float* bi     = (const float*)d_in[11];
    const float* W_ih   = (const float*)d_in[12];
    const float* W_hh   = (const float*)d_in[13];
    const float* b_ih   = (const float*)d_in[14];
    const float* b_hh   = (const float*)d_in[15];
    const float* num_w  = (const float*)d_in[16];
    const float* num_b  = (const float*)d_in[17];
    const float* cls    = (const float*)d_in[18];
    const float* W1     = (const float*)d_in[19];
    const float* b1     = (const float*)d_in[20];
    const float* W2     = (const float*)d_in[21];
    const float* b2     = (const float*)d_in[22];
    float* out = (float*)d_out;

    size_t smem4a = (size_t)(GPHP + CHUNK*SXS) * sizeof(float);   /* ~60 KB */
    cudaFuncSetAttribute(k_attn, cudaFuncAttributeMaxDynamicSharedMemorySize, (int)smem4a);

    k_hyper<<<1,512>>>(z,Wh,bh,Wc,bc,Wi,bi,W_ih,W_hh,b_ih,b_hh,W1,b1);
    k_stable<<<(SECTORS*D+7)/8, 256>>>(emb,Wsp,bsp);
    k_e_all<<<EBLKS, 256>>>(W2,b2);
    k_gramfin<<<HNUM*NN,256>>>(num_w,num_b,cls);     /* 4th launch -> ncu */

    k_attn<<<NCHUNKS*HNUM,512,smem4a>>>(X,sector,out);
    k_final<<<(BATCH+7)/8,256>>>(X,sector,out);
}

// round 15
// speedup vs baseline: 1.2857x; 1.0406x over previous
#include <cuda_runtime.h>
#include <math.h>

#define D        64
#define DIMV     256
#define HNUM     4
#define NN       65
#define HIDDEN   512
#define SECTORS  11
#define BATCH    4096
#define QW_CNT   16640      /* N*DIM */
#define OW_OFF   16640
#define OB_OFF   82176
#define EDIM_ALL 82689
#define CHUNK    38
#define NCHUNKS  108                       /* 108*38 = 4104 >= 4096 */
#define DP       65                        /* padded row stride in gram smem */
/* padded Gram layout: per (h,m) a 65x66 matrix, element [r][j] at r*66+j+1 */
#define GPM      (NN*66)                   /* 4290 floats per matrix */
#define GPHP     12872                     /* 3*GPM=12870, padded to /4 and 16B */
#define SXS      66                        /* padded x row stride */
#define EROWS_PER_BLK 64                   /* 8 warps x 8 rows */
#define EBLKS    ((EDIM_ALL + EROWS_PER_BLK - 1)/EROWS_PER_BLK)   /* 1293 */

/* ---------------- scratch (static device globals; no allocation) -------- */
__device__ alignas(16) float g_stable[SECTORS*D];
__device__ alignas(16) float g_hidden[HIDDEN];
__device__ alignas(16) float g_qw[QW_CNT];
__device__ alignas(16) float g_ob[DIMV];
__device__ alignas(16) float g_om[DIMV];
__device__ float g_outb;
__device__ float g_C;
__device__ alignas(16) float g_scratch[DIMV*DIMV];   /* raw ow rows */
__device__ alignas(16) float g_gram[HNUM*GPHP];
__device__ alignas(16) float g_Av[HNUM*NN];
__device__ alignas(16) float g_Bv[HNUM*NN];

__device__ __forceinline__ float ex2f(float x){
    float r; asm("ex2.approx.ftz.f32 %0, %1;" : "=f"(r) : "f"(x)); return r;
}

/* ---------------- kernel 1: hyper (block 0) + sector table (blocks 1+) -- */
__global__ void k_hyperstable(const float* __restrict__ z,
                        const float* __restrict__ Wh, const float* __restrict__ bh,
                        const float* __restrict__ Wc, const float* __restrict__ bc,
                        const float* __restrict__ Wi, const float* __restrict__ bi,
                        const float* __restrict__ W_ih, const float* __restrict__ W_hh,
                        const float* __restrict__ b_ih, const float* __restrict__ b_hh,
                        const float* __restrict__ W1, const float* __restrict__ b1,
                        const float* __restrict__ emb, const float* __restrict__ Wsp,
                        const float* __restrict__ bsp)
{
    int t = threadIdx.x;   /* 512 threads */
    if (blockIdx.x > 0) {  /* sector table: 16 outputs per block */
        int w = (blockIdx.x-1)*16 + (t>>5);   /* 0..703 */
        if (w >= SECTORS*D) return;
        int lane = t & 31;
        int sec = w / D, d = w % D;
        const float4* e4 = (const float4*)(emb + sec*DIMV);
        const float4* w4 = (const float4*)(Wsp + d*DIMV);
        float acc = 0.f;
        #pragma unroll
        for (int it=0; it<2; it++) {
            float4 a = e4[it*32+lane]; float4 b = w4[it*32+lane];
            acc = fmaf(a.x,b.x,fmaf(a.y,b.y,fmaf(a.z,b.z,fmaf(a.w,b.w,acc))));
        }
        #pragma unroll
        for (int o=16;o>0;o>>=1) acc += __shfl_xor_sync(0xffffffffu, acc, o);
        if (lane==0) g_stable[w] = acc + bsp[d];
        return;
    }
    __shared__ float sz[D], sh0[D], sc0[D], sinp[D], sg[4*D], sh[D];
    if (t < D) sz[t] = z[t];
    __syncthreads();
    if (t < 3*D) {
        int which = t / D, d = t % D;
        const float* W = (which==0) ? Wh : (which==1) ? Wc : Wi;
        const float* B = (which==0) ? bh : (which==1) ? bc : bi;
        float acc = B[d];
        #pragma unroll 8
        for (int k=0;k<D;k++) acc = fmaf(sz[k], W[d*D+k], acc);
        float v = tanhf(acc);
        if (which==0) sh0[d]=v; else if (which==1) sc0[d]=v; else sinp[d]=v;
    }
    __syncthreads();
    if (t < 4*D) {
        float acc = b_ih[t] + b_hh[t];
        #pragma unroll 8
        for (int k=0;k<D;k++) acc = fmaf(sinp[k], W_ih[t*D+k], acc);
        #pragma unroll 8
        for (int k=0;k<D;k++) acc = fmaf(sh0[k],  W_hh[t*D+k], acc);
        sg[t] = acc;
    }
    __syncthreads();
    if (t < D) {
        float ig = sg[t], fg = sg[D+t], gg = sg[2*D+t], og = sg[3*D+t];
        float si = 1.f/(1.f+expf(-ig));
        float sf = 1.f/(1.f+expf(-fg));
        float so = 1.f/(1.f+expf(-og));
        float c  = sf*sc0[t] + si*tanhf(gg);
        sh[t] = so*tanhf(c);
    }
    __syncthreads();
    {   /* hidden = relu(h @ W1.T + b1), all 512 threads */
        float acc = b1[t];
        #pragma unroll 8
        for (int d=0; d<D; d++) acc = fmaf(sh[d], W1[t*D+d], acc);
        g_hidden[t] = fmaxf(acc, 0.f);
    }
}

/* ---------------- kernel 2: all rows of E = hidden @ W2.T + b2 ----------
   Warp handles 8 rows (up to 32 outstanding LDG.128).                     */
__global__ void __launch_bounds__(256,5)
k_e_all(const float* __restrict__ W2, const float* __restrict__ b2)
{
    __shared__ alignas(16) float sh[HIDDEN];
    int t = threadIdx.x;                 /* 256 */
    for (int i=t;i<HIDDEN;i+=256) sh[i]=g_hidden[i];
    __syncthreads();
    int rbase = (blockIdx.x*8 + (t>>5))*8;
    int lane = t & 31;
    const float4* hv = (const float4*)sh;
    float4 h0 = hv[lane], h1 = hv[32+lane], h2 = hv[64+lane], h3 = hv[96+lane];
    float acc[8];
    #pragma unroll
    for (int rr=0; rr<8; rr++) {
        int r = rbase + rr;
        float a = 0.f;
        if (r < EDIM_ALL) {
            const float4* Wr = (const float4*)(W2 + (size_t)r*HIDDEN);
            float4 w0 = __ldcs(Wr+lane),    w1 = __ldcs(Wr+32+lane);
            float4 w2 = __ldcs(Wr+64+lane), w3 = __ldcs(Wr+96+lane);
            a = fmaf(w0.x,h0.x,fmaf(w0.y,h0.y,fmaf(w0.z,h0.z,w0.w*h0.w)));
            a = fmaf(w1.x,h1.x,fmaf(w1.y,h1.y,fmaf(w1.z,h1.z,fmaf(w1.w,h1.w,a))));
            a = fmaf(w2.x,h2.x,fmaf(w2.y,h2.y,fmaf(w2.z,h2.z,fmaf(w2.w,h2.w,a))));
            a = fmaf(w3.x,h3.x,fmaf(w3.y,h3.y,fmaf(w3.z,h3.z,fmaf(w3.w,h3.w,a))));
        }
        acc[rr] = a;
    }
    #pragma unroll
    for (int rr=0; rr<8; rr++) {
        #pragma unroll
        for (int o=16;o>0;o>>=1) acc[rr] += __shfl_xor_sync(0xffffffffu, acc[rr], o);
    }
    if (lane==0) {
        #pragma unroll
        for (int rr=0; rr<8; rr++) {
            int r = rbase + rr;
            if (r >= EDIM_ALL) break;
            float v = acc[rr] + b2[r];
            if (r < QW_CNT)          g_qw[r] = v;
            else if (r < OB_OFF)     g_scratch[r - OW_OFF] = v;
            else {
                int tt = r - OB_OFF;
                if (tt < 256)        g_ob[tt] = v;
                else if (tt < 512)   g_om[tt-256] = v;
                else                 g_outb = v;
            }
        }
    }
}

/* ---------------- kernel 3: Gram matrices + (i==0) v/C/Av/Bv ------------
   512 threads: fill 2x faster, 16 warps hide L2 latency.                  */
__global__ void __launch_bounds__(512)
k_gramfin(const float* __restrict__ num_w, const float* __restrict__ num_b,
          const float* __restrict__ cls)
{
    int h = blockIdx.x / NN;
    int i = blockIdx.x % NN;
    __shared__ alignas(16) float sA[NN*DP], sB[NN*DP];
    __shared__ alignas(16) float sv[D];
    __shared__ alignas(16) float som[DIMV];
    int t = threadIdx.x;                 /* 512 */
    int w = t >> 5, lane = t & 31;
    bool do_av = (i == 0);
    if (do_av) {
        if (t < 256) som[t] = g_om[t];
        __syncthreads();                 /* block-uniform branch: safe */
        const float4* om4 = (const float4*)som;
        float4 m0 = om4[lane], m1 = om4[32+lane];
        for (int kk=w; kk<D; kk+=16) {
            const float4* row = (const float4*)(g_scratch + (h*D+kk)*256);
            float4 a0 = row[lane], a1 = row[32+lane];
            float acc = fmaf(a0.x,m0.x,fmaf(a0.y,m0.y,fmaf(a0.z,m0.z,a0.w*m0.w)));
            acc = fmaf(a1.x,m1.x,fmaf(a1.y,m1.y,fmaf(a1.z,m1.z,fmaf(a1.w,m1.w,acc))));
            #pragma unroll
            for (int o=16;o>0;o>>=1) acc += __shfl_xor_sync(0xffffffffu, acc, o);
            if (lane==0) sv[kk] = acc;
        }
        if (h==0 && w==0) {   /* C */
            float c = 0.f;
            #pragma unroll
            for (int q=0;q<8;q++) {
                int idx = q*32 + lane;
                c += (g_ob[idx] + cls[idx]) * som[idx];
            }
            #pragma unroll
            for (int o=16;o>0;o>>=1) c += __shfl_xor_sync(0xffffffffu, c, o);
            if (lane==0) g_C = c + g_outb;
        }
    }
    for (int idx=t; idx<NN*D; idx+=512) {
        int j = idx / D, d = idx % D;
        float q = g_qw[j*DIMV + h*D + d];
        float a, b;
        if (j==0) { a = 0.f; b = cls[h*D+d]*q; }
        else {
            a = num_w[(j-1)*DIMV + h*D + d]*q;
            b = num_b[(j-1)*DIMV + h*D + d]*q;
        }
        sA[j*DP+d]=a; sB[j*DP+d]=b;
    }
    __syncthreads();
    /* fold softmax scale AND log2(e) so attention can use raw ex2 */
    const float scale = 0.125f * 1.4426950408889634f;
    if (t < 3*NN) {
        int m = t / NN, j = t % NN;
        const float* P = (m==2) ? sB : sA;
        const float* Q = (m==0) ? sA : sB;
        const float* pr = P + i*DP;
        const float* qr = Q + j*DP;
        float acc=0.f;
        #pragma unroll 16
        for (int d=0; d<D; d++) acc = fmaf(pr[d], qr[d], acc);
        g_gram[h*GPHP + m*GPM + i*66 + j + 1] = scale*acc;
    }
    if (do_av && t >= 256 && t < 256 + 2*NN) {
        int tt = t - 256;
        int sel = tt / NN, j = tt % NN;
        const float* row = (sel==0 ? sA : sB) + j*DP;
        float acc = 0.f;
        #pragma unroll 16
        for (int d=0; d<D; d++) acc = fmaf(row[d], sv[d], acc);
        if (sel==0) g_Av[h*NN+j] = acc; else g_Bv[h*NN+j] = acc;
    }
}

/* ---------------- kernel 4: attention logits + softmax (main) -----------
   One head per block, 512 thr, 3 CTAs/SM (proven R12-R14 config).        */
__global__ void __launch_bounds__(512,3)
k_attn(const float* __restrict__ X, const int* __restrict__ sector,
       float* __restrict__ out)
{
    extern __shared__ float smem[];
    float* sg = smem;                    /* GPHP floats: this head's Gram */
    float* sx = smem + GPHP;             /* CHUNK*66; x_j at c*66+j+1 */
    __shared__ int ssec[CHUNK];
    int t = threadIdx.x;                 /* 512 */
    int chunk = blockIdx.x >> 2;
    int h     = blockIdx.x & 3;
    {
        const float4* src = (const float4*)(g_gram + h*GPHP);
        float4* dst = (float4*)sg;
        for (int i=t; i<GPHP/4; i+=512) dst[i] = src[i];
    }
    int b0 = chunk * CHUNK;
    int nch = min(CHUNK, BATCH - b0);    /* 38 or 30: both even */
    if (t < nch) ssec[t] = sector[b0+t];
    __syncthreads();
    for (int idx=t; idx<nch*NN; idx+=512) {
        int c = idx / NN, j = idx % NN;
        float v = 0.f;
        if (j > 0) {
            int b = b0 + c;
            v = X[b*D + (j-1)] + g_stable[ssec[c]*D + (j-1)];
        }
        sx[c*SXS + j + 1] = v;
    }
    __syncthreads();

    int warp = t >> 5, lane = t & 31;
    float* attn = out + BATCH;
    const long long bstride = (long long)HNUM*NN*NN;
    const float* AAs = sg;
    const float* ABs = sg + GPM;
    const float* BBs = sg + 2*GPM;
    for (int i = warp; i < NN; i += 16) {
        float aa0 = AAs[i*66 + 2 + lane],  aa1 = AAs[i*66 + 34 + lane];
        float ab0 = ABs[i*66 + 2 + lane],  ab1 = ABs[i*66 + 34 + lane];
        float bb0 = BBs[i*66 + 2 + lane],  bb1 = BBs[i*66 + 34 + lane];
        float ba0 = ABs[(1+lane)*66 + i + 1];
        float ba1 = ABs[(33+lane)*66 + i + 1];
        float ab0c = ABs[i*66 + 1];      /* AB[i,0] (lane-uniform) */
        float bb0c = BBs[i*66 + 1];      /* BB[i,0] */
        float* row = attn + (long long)b0*bstride + ((h*NN + i)*(long long)NN);
        for (int c=0; c<nch; c+=2) {
            const float* xA = sx + c*SXS;
            const float* xB = xA + SXS;
            float xiA = xA[i+1],   xiB = xB[i+1];
            float xj0A = xA[2+lane],  xj1A = xA[34+lane];
            float xj0B = xB[2+lane],  xj1B = xB[34+lane];
            float e0A = ex2f(fmaf(xiA, fmaf(xj0A,aa0,ab0), fmaf(xj0A,ba0,bb0)));
            float e1A = ex2f(fmaf(xiA, fmaf(xj1A,aa1,ab1), fmaf(xj1A,ba1,bb1)));
            float e0B = ex2f(fmaf(xiB, fmaf(xj0B,aa0,ab0), fmaf(xj0B,ba0,bb0)));
            float e1B = ex2f(fmaf(xiB, fmaf(xj1B,aa1,ab1), fmaf(xj1B,ba1,bb1)));
            float ecA = ex2f(fmaf(xiA, ab0c, bb0c));   /* col 0, uniform */
            float ecB = ex2f(fmaf(xiB, ab0c, bb0c));
            float sA = e0A + e1A;
            float sB = e0B + e1B;
            #pragma unroll
            for (int o=16;o>0;o>>=1) {
                sA += __shfl_xor_sync(0xffffffffu, sA, o);
                sB += __shfl_xor_sync(0xffffffffu, sB, o);
            }
            float rA = __fdividef(1.f, sA + ecA);
            float rB = __fdividef(1.f, sB + ecB);
            float* rowB = row + bstride;
            __stcs(row  + 1 + lane,  e0A*rA);
            __stcs(row  + 33 + lane, e1A*rA);
            __stcs(rowB + 1 + lane,  e0B*rB);
            __stcs(rowB + 33 + lane, e1B*rB);
            if (lane==0) {
                __stcs(row,  ecA*rA);
                __stcs(rowB, ecB*rB);
            }
            row += 2*bstride;
        }
    }
}

/* ---------------- kernel 5: final[b] = C + sum p.(x.Av + Bv) ------------ */
__global__ void __launch_bounds__(256,1)
k_final(const float* __restrict__ X, const int* __restrict__ sector,
        float* __restrict__ out)
{
    __shared__ float sAv[HNUM*NN], sBv[HNUM*NN];
    int t = threadIdx.x;                 /* 256 */
    for (int i=t; i<HNUM*NN; i+=256) { sAv[i] = g_Av[i]; sBv[i] = g_Bv[i]; }
    __syncthreads();
    int wid = t >> 5, lane = t & 31;
    int b = blockIdx.x*8 + wid;
    if (b >= BATCH) return;
    int sec = sector[b];
    const float* Xb = X + b*D;
    const float* st = g_stable + sec*D;
    float x0 = (lane>0) ? (Xb[lane-1]  + st[lane-1])  : 0.f;   /* j=lane     */
    float x1 =            Xb[lane+31] + st[lane+31];           /* j=lane+32  */
    float x2 = (lane==0)? (Xb[63]      + st[63])      : 0.f;   /* j=64       */
    const float* attn = out + BATCH;
    const float* p = attn + ((long long)b*HNUM)*NN*NN;   /* rows i=0 of 4 heads */
    float acc = 0.f;
    #pragma unroll
    for (int h=0; h<HNUM; h++) {
        const float* ph = p + (long long)h*NN*NN;        /* row i=0 */
        float p0 = ph[lane];
        float p1 = ph[lane+32];
        acc = fmaf(p0, fmaf(x0, sAv[h*NN+lane],    sBv[h*NN+lane]),    acc);
        acc = fmaf(p1, fmaf(x1, sAv[h*NN+lane+32], sBv[h*NN+lane+32]), acc);
        if (lane==0) {
            float p2 = ph[64];
            acc = fmaf(p2, fmaf(x2, sAv[h*NN+64], sBv[h*NN+64]), acc);
        }
    }
    #pragma unroll
    for (int o=16;o>0;o>>=1) acc += __shfl_xor_sync(0xffffffffu, acc, o);
    if (lane==0) out[b] = acc + g_C;
}

/* ---------------- launch ------------------------------------------------ */
extern "C" void kernel_launch(void* const* d_in, const int* in_sizes, int n_in,
                              void* d_out, int out_size)
{
    const float* X      = (const float*)d_in[0];
    const float* z      = (const float*)d_in[1];
    const int*   sector = (const int*)  d_in[2];
    const float* emb    = (const float*)d_in[3];
    const float* Wsp    = (const float*)d_in[4];
    const float* bsp    = (const float*)d_in[5];
    const float* Wh     = (const float*)d_in[6];
    const float* bh     = (const float*)d_in[7];
    const float* Wc     = (const float*)d_in[8];
    const float* bc     = (const float*)d_in[9];
    const float* Wi     = (const float*)d_in[10];
    const float* bi     = (const float*)d_in[11];
    const float* W_ih   = (const float*)d_in[12];
    const float* W_hh   = (const float*)d_in[13];
    const float* b_ih   = (const float*)d_in[14];
    const float* b_hh   = (const float*)d_in[15];
    const float* num_w  = (const float*)d_in[16];
    const float* num_b  = (const float*)d_in[17];
    const float* cls    = (const float*)d_in[18];
    const float* W1     = (const float*)d_in[19];
    const float* b1     = (const float*)d_in[20];
    const float* W2     = (const float*)d_in[21];
    const float* b2     = (const float*)d_in[22];
    float* out = (float*)d_out;

    size_t smem4a = (size_t)(GPHP + CHUNK*SXS) * sizeof(float);   /* ~60 KB */
    cudaFuncSetAttribute(k_attn, cudaFuncAttributeMaxDynamicSharedMemorySize, (int)smem4a);

    int nsb = 1 + (SECTORS*D + 15)/16;   /* 1 hyper block + 44 stable blocks */
    k_hyperstable<<<nsb,512>>>(z,Wh,bh,Wc,bc,Wi,bi,W_ih,W_hh,b_ih,b_hh,W1,b1,
                               emb,Wsp,bsp);
    k_e_all<<<EBLKS, 256>>>(W2,b2);
    k_gramfin<<<HNUM*NN,512>>>(num_w,num_b,cls);

    k_attn<<<NCHUNKS*HNUM,512,smem4a>>>(X,sector,out);   /* 4th -> ncu capture */
    k_final<<<(BATCH+7)/8,256>>>(X,sector,out);
}